// round 6
// baseline (speedup 1.0000x reference)
#include <cuda_runtime.h>
#include <cuda_bf16.h>

// Problem constants (fixed by setup_inputs)
#define B_ 64
#define N_ 1024
#define E_ 16384
#define D_ 1024
#define C_ 128

#define NB 132          // co-resident blocks (<= 148 SMs on sm_103a; 1 block/SM)
#define NT 256
#define GSZ (NB * NT)

// ---------------- device scratch (static, no allocations) ----------------
__device__ int   g_src[E_], g_dst[E_];
__device__ int   g_deg[N_];
__device__ float g_degf[N_];
__device__ int   g_rowptr[N_ + 1];
__device__ int   g_col[E_];
__device__ int   g_flag2[N_], g_flag3[N_];
__device__ int   g_list2[N_], g_list3[N_];
__device__ int   g_c2, g_c3;
__device__ float g_w0[B_ * C_];         // (h0 @ W_conv) per batch
__device__ float g_H2[B_ * N_ * C_];    // node-indexed (frontier2 rows valid)
__device__ float g_H3[B_ * N_ * C_];    // node-indexed (frontier3 rows valid)

// ---------------- software grid barrier (all blocks resident) ----------------
__device__ volatile unsigned g_gen;     // generation ticket (persists across launches)
__device__ unsigned          g_count;

__device__ __forceinline__ void gsync(unsigned gen0, unsigned k) {
    __syncthreads();
    if (threadIdx.x == 0) {
        __threadfence();
        if (atomicAdd(&g_count, 1u) == NB - 1u) {
            g_count = 0u;
            __threadfence();
            g_gen = gen0 + k;                 // release
        } else {
            while (g_gen != gen0 + k) { }     // spin (volatile)
        }
        __threadfence();
    }
    __syncthreads();
}

// inclusive scan of per-thread totals across 256 threads (single block)
__device__ __forceinline__ int scan_tot(int T, int t, int* s) {
    s[t] = T;
    __syncthreads();
#pragma unroll
    for (int off = 1; off < 256; off <<= 1) {
        int v = (t >= off) ? s[t - off] : 0;
        __syncthreads();
        s[t] += v;
        __syncthreads();
    }
    int r = s[t];
    __syncthreads();
    return r;
}

// stable compaction of a 0/1 flag array [N_] -> list + count (single block)
__device__ __forceinline__ void compact_flags(const int* flags, int* list, int* cnt_out,
                                              int t, int* s) {
    int base = 4 * t;
    int f0 = flags[base + 0], f1 = flags[base + 1];
    int f2 = flags[base + 2], f3 = flags[base + 3];
    int T = f0 + f1 + f2 + f3;
    int incl = scan_tot(T, t, s);
    int pos = incl - T;
    if (f0) list[pos] = base + 0; pos += f0;
    if (f1) list[pos] = base + 1; pos += f1;
    if (f2) list[pos] = base + 2; pos += f2;
    if (f3) list[pos] = base + 3; pos += f3;
    if (t == 255) *cnt_out = incl;
}

__global__ __launch_bounds__(NT) void k_mega(
    const float* __restrict__ x, const void* __restrict__ eidx,
    const float* __restrict__ W_emb,  const float* __restrict__ b_emb,
    const float* __restrict__ W_conv, const float* __restrict__ b_conv,
    const float* __restrict__ W_cls,  const float* __restrict__ b_cls,
    float* __restrict__ out)
{
    __shared__ __align__(16) float sm[2048];     // 8 KB, unioned across phases
    const int t   = threadIdx.x;
    const int bid = blockIdx.x;
    const int gtid = bid * NT + t;
    const unsigned gen0 = g_gen;                 // stable: prior launch fully done

    // ---------------- P0: dtype detect (per-block, local) + convert + clear ----
    {
        const unsigned* ew32 = (const unsigned*)eidx;
        int any = __syncthreads_or(ew32[2 * t + 1] != 0u);
        int is64 = !any;                          // int64 => all high words zero
        for (int i = gtid; i < E_; i += GSZ) {
            if (is64) {
                const long long* p = (const long long*)eidx;
                g_src[i] = (int)p[i];
                g_dst[i] = (int)p[E_ + i];
            } else {
                const int* p = (const int*)eidx;
                g_src[i] = p[i];
                g_dst[i] = p[E_ + i];
            }
        }
        for (int i = gtid; i < N_; i += GSZ) { g_deg[i] = 0; g_flag2[i] = 0; g_flag3[i] = 0; }
    }
    gsync(gen0, 1);

    // ---------------- P1: deg+flag3 (blocks 0..15)  ||  embedding (blocks 16..79)
    if (bid < 16) {
        for (int e = bid * NT + t; e < E_; e += 16 * NT) {
            int d = g_dst[e];
            atomicAdd(&g_deg[d], 1);
            if (d == 0) g_flag3[g_src[e]] = 1;
        }
    } else if (bid < 16 + B_) {
        int b = bid - 16;
        float* xs   = sm;            // [1024]
        float* part = sm + D_;       // [256]
        float* h0   = sm + D_ + NT;  // [128]
        for (int d = t; d < D_; d += NT) xs[d] = x[b * D_ + d];
        __syncthreads();
        int c = t & 127, half = t >> 7;
        float a0 = 0.f, a1 = 0.f;
        int d0 = half * (D_ / 2);
#pragma unroll 4
        for (int d = d0; d < d0 + D_ / 2; d += 4) {
            float4 xv = *(const float4*)&xs[d];
            a0 += xv.x * W_emb[(d + 0) * C_ + c];
            a1 += xv.y * W_emb[(d + 1) * C_ + c];
            a0 += xv.z * W_emb[(d + 2) * C_ + c];
            a1 += xv.w * W_emb[(d + 3) * C_ + c];
        }
        part[t] = a0 + a1;
        __syncthreads();
        if (half == 0) h0[c] = fmaxf(part[c] + part[c + 128] + b_emb[c], 0.f);
        __syncthreads();
        if (half == 0) {
            float a2 = 0.f;
#pragma unroll 8
            for (int k = 0; k < C_; k++) a2 += h0[k] * W_conv[k * C_ + c];
            g_w0[b * C_ + c] = a2;
        }
    }
    gsync(gen0, 2);

    // ---------------- P2: flag2 (0..15)  ||  rowptr scan (130)  ||  flag3 compact (129)
    if (bid < 16) {
        for (int e = bid * NT + t; e < E_; e += 16 * NT) {
            if (g_flag3[g_dst[e]]) g_flag2[g_src[e]] = 1;
        }
    } else if (bid == 130) {
        int base = 4 * t;
        int d0 = g_deg[base + 0], d1 = g_deg[base + 1];
        int d2 = g_deg[base + 2], d3 = g_deg[base + 3];
        g_degf[base + 0] = (float)d0; g_degf[base + 1] = (float)d1;
        g_degf[base + 2] = (float)d2; g_degf[base + 3] = (float)d3;
        int T = d0 + d1 + d2 + d3;
        int incl = scan_tot(T, t, (int*)sm);
        int run = incl - T;
        run += d0; g_rowptr[base + 1] = run;
        run += d1; g_rowptr[base + 2] = run;
        run += d2; g_rowptr[base + 3] = run;
        run += d3; g_rowptr[base + 4] = run;
        if (t == 0) g_rowptr[0] = 0;
    } else if (bid == 129) {
        compact_flags(g_flag3, g_list3, &g_c3, t, (int*)sm);
    }
    gsync(gen0, 3);

    // ---------------- P3: flag2 compact (131)  ||  csrfill (0..130)
    if (bid == 131) {
        compact_flags(g_flag2, g_list2, &g_c2, t, (int*)sm);
    } else {
        int warp = t >> 5, lane = t & 31;
        for (int n = bid * 8 + warp; n < N_; n += 131 * 8) {
            if (!(g_flag2[n] | g_flag3[n] | (n == 0))) continue;
            int base = g_rowptr[n], cnt = 0;
            for (int e0 = 0; e0 < E_; e0 += 32) {
                int e = e0 + lane;
                bool m = (g_dst[e] == n);
                unsigned mask = __ballot_sync(0xffffffffu, m);
                if (m) g_col[base + cnt + __popc(mask & ((1u << lane) - 1u))] = g_src[e];
                cnt += __popc(mask);
            }
        }
    }
    gsync(gen0, 4);

    // ---------------- P4: conv2 fused agg(analytic conv1) + GEMM + relu (all blocks)
    {
        int cnt2 = g_c2;
        int M = B_ * cnt2;
        int ntiles = (M + 15) >> 4;
        int c = t & 127, rg = t >> 7;
        float bc = b_conv[c];
        float (*As)[C_] = (float (*)[C_])sm;
        for (int tile = bid; tile < ntiles; tile += NB) {
            int r0 = tile * 16;
            for (int r = rg * 8; r < rg * 8 + 8; r++) {
                int rr = r0 + r;
                if (rr < M) {
                    int b = rr / cnt2, i = rr - b * cnt2;
                    int n = g_list2[i];
                    int s0 = g_rowptr[n], s1 = g_rowptr[n + 1];
                    float wb = g_w0[b * C_ + c];
                    float acc = 0.f;
#pragma unroll 4
                    for (int q = s0; q < s1; q++)
                        acc += fmaxf(g_degf[g_col[q]] * wb + bc, 0.f);
                    As[r][c] = acc;
                } else {
                    As[r][c] = 0.f;
                }
            }
            __syncthreads();
            float acc[8] = {0.f, 0.f, 0.f, 0.f, 0.f, 0.f, 0.f, 0.f};
#pragma unroll 8
            for (int k = 0; k < C_; k += 4) {
                float w0 = W_conv[(k + 0) * C_ + c];
                float w1 = W_conv[(k + 1) * C_ + c];
                float w2 = W_conv[(k + 2) * C_ + c];
                float w3 = W_conv[(k + 3) * C_ + c];
#pragma unroll
                for (int r = 0; r < 8; r++) {
                    float4 a = *(const float4*)&As[rg * 8 + r][k];
                    acc[r] += a.x * w0; acc[r] += a.y * w1;
                    acc[r] += a.z * w2; acc[r] += a.w * w3;
                }
            }
            for (int r = 0; r < 8; r++) {
                int rr = r0 + rg * 8 + r;
                if (rr < M) {
                    int b = rr / cnt2, i = rr - b * cnt2;
                    g_H2[(b * N_ + g_list2[i]) * C_ + c] = fmaxf(acc[r] + bc, 0.f);
                }
            }
            __syncthreads();
        }
    }
    gsync(gen0, 5);

    // ---------------- P5: conv3 fused agg + GEMM + relu (all blocks)
    {
        int cnt3 = g_c3;
        int M = B_ * cnt3;
        int ntiles = (M + 15) >> 4;
        int c = t & 127, rg = t >> 7;
        float bc = b_conv[c];
        float (*As)[C_] = (float (*)[C_])sm;
        for (int tile = bid; tile < ntiles; tile += NB) {
            int r0 = tile * 16;
            for (int r = rg * 8; r < rg * 8 + 8; r++) {
                int rr = r0 + r;
                if (rr < M) {
                    int b = rr / cnt3, i = rr - b * cnt3;
                    int n = g_list3[i];
                    int s0 = g_rowptr[n], s1 = g_rowptr[n + 1];
                    float acc = 0.f;
#pragma unroll 4
                    for (int q = s0; q < s1; q++)
                        acc += g_H2[(b * N_ + g_col[q]) * C_ + c];
                    As[r][c] = acc;
                } else {
                    As[r][c] = 0.f;
                }
            }
            __syncthreads();
            float acc[8] = {0.f, 0.f, 0.f, 0.f, 0.f, 0.f, 0.f, 0.f};
#pragma unroll 8
            for (int k = 0; k < C_; k += 4) {
                float w0 = W_conv[(k + 0) * C_ + c];
                float w1 = W_conv[(k + 1) * C_ + c];
                float w2 = W_conv[(k + 2) * C_ + c];
                float w3 = W_conv[(k + 3) * C_ + c];
#pragma unroll
                for (int r = 0; r < 8; r++) {
                    float4 a = *(const float4*)&As[rg * 8 + r][k];
                    acc[r] += a.x * w0; acc[r] += a.y * w1;
                    acc[r] += a.z * w2; acc[r] += a.w * w3;
                }
            }
            for (int r = 0; r < 8; r++) {
                int rr = r0 + rg * 8 + r;
                if (rr < M) {
                    int b = rr / cnt3, i = rr - b * cnt3;
                    g_H3[(b * N_ + g_list3[i]) * C_ + c] = fmaxf(acc[r] + bc, 0.f);
                }
            }
            __syncthreads();
        }
    }
    gsync(gen0, 6);

    // ---------------- P6: conv4 agg (node 0) + GEMM + classifier (blocks 0..63)
    if (bid < B_) {
        float* s4  = sm;        // [128]
        float* red = sm + C_;   // [128]
        int b = bid;
        if (t < C_) {
            int s0 = g_rowptr[0], s1 = g_rowptr[1];
            float acc = 0.f;
#pragma unroll 4
            for (int q = s0; q < s1; q++)
                acc += g_H3[(b * N_ + g_col[q]) * C_ + t];
            s4[t] = acc;
        }
        __syncthreads();
        if (t < C_) {
            float a2 = b_conv[t];
#pragma unroll 8
            for (int k = 0; k < C_; k++) a2 += s4[k] * W_conv[k * C_ + t];
            red[t] = fmaxf(a2, 0.f) * W_cls[t];
        }
        __syncthreads();
        for (int off = 64; off > 0; off >>= 1) {
            if (t < off) red[t] += red[t + off];
            __syncthreads();
        }
        if (t == 0) out[b] = red[0] + b_cls[0];
    }
}

extern "C" void kernel_launch(void* const* d_in, const int* in_sizes, int n_in,
                              void* d_out, int out_size) {
    (void)in_sizes; (void)n_in; (void)out_size;
    const float* x      = (const float*)d_in[0];
    const void*  eidx   = d_in[1];
    const float* W_emb  = (const float*)d_in[2];
    const float* b_emb  = (const float*)d_in[3];
    const float* W_conv = (const float*)d_in[4];
    const float* b_conv = (const float*)d_in[5];
    const float* W_cls  = (const float*)d_in[6];
    const float* b_cls  = (const float*)d_in[7];
    float* out = (float*)d_out;

    k_mega<<<NB, NT>>>(x, eidx, W_emb, b_emb, W_conv, b_conv, W_cls, b_cls, out);
}

// round 7
// speedup vs baseline: 2.1156x; 2.1156x over previous
#include <cuda_runtime.h>
#include <cuda_bf16.h>

// Problem constants (fixed by setup_inputs)
#define B_ 64
#define N_ 1024
#define E_ 16384
#define D_ 1024
#define C_ 128

#define NB 132          // 1 block per SM (<=148) -> co-residency guaranteed
#define NT 1024
#define GSZ (NB * NT)

// ---------------- device scratch (static, no allocations) ----------------
__device__ int   g_src[E_], g_dst[E_];
__device__ int   g_deg[N_];
__device__ float g_degf[N_];
__device__ int   g_rowptr[N_ + 1];
__device__ int   g_col[E_];
__device__ int   g_flag2[N_], g_flag3[N_];
__device__ int   g_list2[N_], g_list3[N_];
__device__ int   g_c2, g_c3;
__device__ float g_w0[B_ * C_];         // (h0 @ W_conv) per batch
__device__ float g_H2[B_ * N_ * C_];    // node-indexed (frontier2 rows valid)
__device__ float g_H3[B_ * N_ * C_];    // node-indexed (frontier3 rows valid)

// ---------------- software grid barrier (all blocks resident) ----------------
__device__ volatile unsigned g_gen;     // generation ticket (persists across launches)
__device__ unsigned          g_count;

__device__ __forceinline__ void gsync(unsigned gen0, unsigned k) {
    __syncthreads();
    if (threadIdx.x == 0) {
        __threadfence();
        if (atomicAdd(&g_count, 1u) == NB - 1u) {
            g_count = 0u;
            __threadfence();
            g_gen = gen0 + k;                 // release
        } else {
            while (g_gen != gen0 + k) { __nanosleep(64); }
        }
        __threadfence();
    }
    __syncthreads();
}

// inclusive scan of one value per thread across 1024 threads (single block)
__device__ __forceinline__ int scan1(int v, int t, int* s) {
    s[t] = v;
    __syncthreads();
#pragma unroll
    for (int off = 1; off < NT; off <<= 1) {
        int u = (t >= off) ? s[t - off] : 0;
        __syncthreads();
        s[t] += u;
        __syncthreads();
    }
    int r = s[t];
    __syncthreads();
    return r;
}

// stable compaction of a 0/1 flag array [N_] -> list + count (single block)
__device__ __forceinline__ void compact_flags(const int* flags, int* list, int* cnt_out,
                                              int t, int* s) {
    int f = flags[t];
    int incl = scan1(f, t, s);
    if (f) list[incl - 1] = t;
    if (t == NT - 1) *cnt_out = incl;
}

__global__ __launch_bounds__(NT) void k_mega(
    const float* __restrict__ x, const void* __restrict__ eidx,
    const float* __restrict__ W_emb,  const float* __restrict__ b_emb,
    const float* __restrict__ W_conv, const float* __restrict__ b_conv,
    const float* __restrict__ W_cls,  const float* __restrict__ b_cls,
    float* __restrict__ out)
{
    __shared__ __align__(16) float sm[8192];     // 32 KB, unioned across phases
    const int t    = threadIdx.x;
    const int bid  = blockIdx.x;
    const int gtid = bid * NT + t;
    const unsigned gen0 = g_gen;                 // stable: prior launch fully done

    // ---------------- P0: dtype detect (per-block) + convert + clear ----------
    {
        const unsigned* ew32 = (const unsigned*)eidx;
        int any = __syncthreads_or(ew32[2 * t + 1] != 0u);
        int is64 = !any;                          // int64 => high words all zero
        for (int i = gtid; i < E_; i += GSZ) {
            if (is64) {
                const long long* p = (const long long*)eidx;
                g_src[i] = (int)p[i];
                g_dst[i] = (int)p[E_ + i];
            } else {
                const int* p = (const int*)eidx;
                g_src[i] = p[i];
                g_dst[i] = p[E_ + i];
            }
        }
        for (int i = gtid; i < N_; i += GSZ) { g_deg[i] = 0; g_flag2[i] = 0; g_flag3[i] = 0; }
    }
    gsync(gen0, 1);

    // ---------------- P1: deg+flag3 (blocks 0..15) || embedding (blocks 16..79)
    if (bid < 16) {
        int e = bid * NT + t;                     // 16*1024 == E_
        int d = g_dst[e];
        atomicAdd(&g_deg[d], 1);
        if (d == 0) g_flag3[g_src[e]] = 1;
    } else if (bid < 16 + B_) {
        int b = bid - 16;
        float* xs   = sm;             // [1024]
        float* part = sm + D_;        // [1024] (8 slices x 128)
        float* h0   = sm + 2 * D_;    // [128]
        xs[t] = x[b * D_ + t];
        __syncthreads();
        int c = t & 127, ds = t >> 7;             // 8 d-slices of 128
        int d0 = ds * 128;
        float a0 = 0.f, a1 = 0.f;
#pragma unroll 4
        for (int d = d0; d < d0 + 128; d += 4) {
            float4 xv = *(const float4*)&xs[d];
            a0 += xv.x * W_emb[(d + 0) * C_ + c];
            a1 += xv.y * W_emb[(d + 1) * C_ + c];
            a0 += xv.z * W_emb[(d + 2) * C_ + c];
            a1 += xv.w * W_emb[(d + 3) * C_ + c];
        }
        part[ds * C_ + c] = a0 + a1;
        __syncthreads();
        if (ds == 0) {
            float h = b_emb[c];
#pragma unroll
            for (int s = 0; s < 8; s++) h += part[s * C_ + c];
            h0[c] = fmaxf(h, 0.f);
        }
        __syncthreads();
        // w0[b] = h0 @ W_conv, split over 8 k-slices of 16
        float p2 = 0.f;
        int k0 = ds * 16;
#pragma unroll
        for (int k = k0; k < k0 + 16; k++) p2 += h0[k] * W_conv[k * C_ + c];
        part[ds * C_ + c] = p2;
        __syncthreads();
        if (ds == 0) {
            float a2 = 0.f;
#pragma unroll
            for (int s = 0; s < 8; s++) a2 += part[s * C_ + c];
            g_w0[b * C_ + c] = a2;
        }
    }
    gsync(gen0, 2);

    // ---------------- P2: flag2 (0..15) || rowptr scan (130) || flag3 compact (129)
    if (bid < 16) {
        int e = bid * NT + t;
        if (g_flag3[g_dst[e]]) g_flag2[g_src[e]] = 1;
    } else if (bid == 130) {
        int d = g_deg[t];
        g_degf[t] = (float)d;
        int incl = scan1(d, t, (int*)sm);
        g_rowptr[t + 1] = incl;
        if (t == 0) g_rowptr[0] = 0;
    } else if (bid == 129) {
        compact_flags(g_flag3, g_list3, &g_c3, t, (int*)sm);
    }
    gsync(gen0, 3);

    // ---------------- P3: flag2 compact (131) || csrfill (0..130, 4 warps/node)
    if (bid == 131) {
        compact_flags(g_flag2, g_list2, &g_c2, t, (int*)sm);
    } else {
        int wg    = bid * 8 + (t >> 7);           // 0..1047, one node per warp-group
        int w     = (t >> 5) & 3;                 // warp within group (quarter of edges)
        int lane  = t & 31;
        int* cnts = (int*)sm;                     // [8][4]
        bool act = (wg < N_) && (g_flag2[wg] | g_flag3[wg] | (wg == 0));
        int my = 0;
        if (act) {
            int e0 = w * (E_ / 4);
            for (int e = e0 + lane; e < e0 + E_ / 4; e += 32) {
                unsigned mask = __ballot_sync(0xffffffffu, g_dst[e] == wg);
                my += __popc(mask);
            }
        }
        if (lane == 0) cnts[(t >> 7) * 4 + w] = my;
        __syncthreads();
        if (act) {
            int base = g_rowptr[wg];
            for (int j = 0; j < w; j++) base += cnts[(t >> 7) * 4 + j];
            int cnt = 0;
            int e0 = w * (E_ / 4);
            for (int e = e0 + lane; e < e0 + E_ / 4; e += 32) {
                bool m = (g_dst[e] == wg);
                unsigned mask = __ballot_sync(0xffffffffu, m);
                if (m) g_col[base + cnt + __popc(mask & ((1u << lane) - 1u))] = g_src[e];
                cnt += __popc(mask);
            }
        }
    }
    gsync(gen0, 4);

    // ---------------- P4: conv2 fused agg(analytic conv1) + GEMM + relu -------
    {
        int cnt2 = g_c2;
        int M = B_ * cnt2;
        int ntiles = (M + 63) >> 6;
        int c = t & 127, rg = t >> 7;             // 8 row-groups x 8 rows
        float bc = b_conv[c];
        float (*As)[C_] = (float (*)[C_])sm;      // [64][128]
        for (int tile = bid; tile < ntiles; tile += NB) {
            int r0 = tile * 64;
            for (int r = rg * 8; r < rg * 8 + 8; r++) {
                int rr = r0 + r;
                if (rr < M) {
                    int b = rr / cnt2, i = rr - b * cnt2;
                    int n = g_list2[i];
                    int s0 = g_rowptr[n], s1 = g_rowptr[n + 1];
                    float wb = g_w0[b * C_ + c];
                    float acc = 0.f;
#pragma unroll 4
                    for (int q = s0; q < s1; q++)
                        acc += fmaxf(g_degf[g_col[q]] * wb + bc, 0.f);
                    As[r][c] = acc;
                } else {
                    As[r][c] = 0.f;
                }
            }
            __syncthreads();
            float acc[8] = {0.f, 0.f, 0.f, 0.f, 0.f, 0.f, 0.f, 0.f};
#pragma unroll 8
            for (int k = 0; k < C_; k += 4) {
                float w0 = W_conv[(k + 0) * C_ + c];
                float w1 = W_conv[(k + 1) * C_ + c];
                float w2 = W_conv[(k + 2) * C_ + c];
                float w3 = W_conv[(k + 3) * C_ + c];
#pragma unroll
                for (int r = 0; r < 8; r++) {
                    float4 a = *(const float4*)&As[rg * 8 + r][k];
                    acc[r] += a.x * w0; acc[r] += a.y * w1;
                    acc[r] += a.z * w2; acc[r] += a.w * w3;
                }
            }
            for (int r = 0; r < 8; r++) {
                int rr = r0 + rg * 8 + r;
                if (rr < M) {
                    int b = rr / cnt2, i = rr - b * cnt2;
                    g_H2[(b * N_ + g_list2[i]) * C_ + c] = fmaxf(acc[r] + bc, 0.f);
                }
            }
            __syncthreads();
        }
    }
    gsync(gen0, 5);

    // ---------------- P5: conv3 fused agg + GEMM + relu ------------------------
    {
        int cnt3 = g_c3;
        int M = B_ * cnt3;
        int ntiles = (M + 63) >> 6;
        int c = t & 127, rg = t >> 7;
        float bc = b_conv[c];
        float (*As)[C_] = (float (*)[C_])sm;
        for (int tile = bid; tile < ntiles; tile += NB) {
            int r0 = tile * 64;
            for (int r = rg * 8; r < rg * 8 + 8; r++) {
                int rr = r0 + r;
                if (rr < M) {
                    int b = rr / cnt3, i = rr - b * cnt3;
                    int n = g_list3[i];
                    int s0 = g_rowptr[n], s1 = g_rowptr[n + 1];
                    float acc = 0.f;
#pragma unroll 4
                    for (int q = s0; q < s1; q++)
                        acc += g_H2[(b * N_ + g_col[q]) * C_ + c];
                    As[r][c] = acc;
                } else {
                    As[r][c] = 0.f;
                }
            }
            __syncthreads();
            float acc[8] = {0.f, 0.f, 0.f, 0.f, 0.f, 0.f, 0.f, 0.f};
#pragma unroll 8
            for (int k = 0; k < C_; k += 4) {
                float w0 = W_conv[(k + 0) * C_ + c];
                float w1 = W_conv[(k + 1) * C_ + c];
                float w2 = W_conv[(k + 2) * C_ + c];
                float w3 = W_conv[(k + 3) * C_ + c];
#pragma unroll
                for (int r = 0; r < 8; r++) {
                    float4 a = *(const float4*)&As[rg * 8 + r][k];
                    acc[r] += a.x * w0; acc[r] += a.y * w1;
                    acc[r] += a.z * w2; acc[r] += a.w * w3;
                }
            }
            for (int r = 0; r < 8; r++) {
                int rr = r0 + rg * 8 + r;
                if (rr < M) {
                    int b = rr / cnt3, i = rr - b * cnt3;
                    g_H3[(b * N_ + g_list3[i]) * C_ + c] = fmaxf(acc[r] + bc, 0.f);
                }
            }
            __syncthreads();
        }
    }
    gsync(gen0, 6);

    // ---------------- P6: conv4 agg (node 0) + GEMM + classifier (blocks 0..63)
    if (bid < B_ && t < C_) {
        float* s4  = sm;        // [128]
        float* red = sm + C_;   // [128]
        int b = bid;
        int s0 = g_rowptr[0], s1 = g_rowptr[1];
        float acc = 0.f;
#pragma unroll 4
        for (int q = s0; q < s1; q++)
            acc += g_H3[(b * N_ + g_col[q]) * C_ + t];
        s4[t] = acc;
        __syncwarp();
        __syncthreads();
        float a2 = b_conv[t];
#pragma unroll 8
        for (int k = 0; k < C_; k++) a2 += s4[k] * W_conv[k * C_ + t];
        red[t] = fmaxf(a2, 0.f) * W_cls[t];
        __syncthreads();
        for (int off = 64; off > 0; off >>= 1) {
            if (t < off) red[t] += red[t + off];
            __syncthreads();
        }
        if (t == 0) out[b] = red[0] + b_cls[0];
    } else if (bid < B_) {
        // non-participating threads of active blocks must match the barrier count
        __syncthreads();            // pairs with s4 barrier
        __syncthreads();            // pairs with red barrier
        for (int off = 64; off > 0; off >>= 1) __syncthreads();
    }
}

extern "C" void kernel_launch(void* const* d_in, const int* in_sizes, int n_in,
                              void* d_out, int out_size) {
    (void)in_sizes; (void)n_in; (void)out_size;
    const float* x      = (const float*)d_in[0];
    const void*  eidx   = d_in[1];
    const float* W_emb  = (const float*)d_in[2];
    const float* b_emb  = (const float*)d_in[3];
    const float* W_conv = (const float*)d_in[4];
    const float* b_conv = (const float*)d_in[5];
    const float* W_cls  = (const float*)d_in[6];
    const float* b_cls  = (const float*)d_in[7];
    float* out = (float*)d_out;

    k_mega<<<NB, NT>>>(x, eidx, W_emb, b_emb, W_conv, b_conv, W_cls, b_cls, out);
}

// round 8
// speedup vs baseline: 2.2615x; 1.0690x over previous
#include <cuda_runtime.h>
#include <cuda_bf16.h>

// Problem constants (fixed by setup_inputs)
#define B_ 64
#define N_ 1024
#define E_ 16384
#define D_ 1024
#define C_ 128

#define NB 132          // 1 block per SM (<=148) -> co-residency guaranteed
#define NT 1024
#define FULLM 0xffffffffu

// ---------------- device scratch (static, no allocations) ----------------
// deg/flag2/flag3 are cleared at the END of each launch (and are zero-init
// at load), so P0 can use them immediately.
__device__ __align__(16) int g_src[E_];
__device__ __align__(16) int g_dst[E_];
__device__ int   g_deg[N_];
__device__ float g_degf[N_];
__device__ int   g_rowptr[N_ + 1];
__device__ int   g_col[E_];
__device__ float g_nbrdeg[E_];          // degf of neighbor, packed per CSR slot
__device__ int   g_flag2[N_], g_flag3[N_];
__device__ int   g_list2[N_], g_list3[N_];
__device__ int   g_c2, g_c3;
__device__ float g_w0[B_ * C_];         // (h0 @ W_conv) per batch
__device__ float g_H2[B_ * N_ * C_];    // node-indexed (frontier2 rows valid)
__device__ float g_H3[B_ * N_ * C_];    // node-indexed (frontier3 rows valid)

// ---------------- software grid barrier (all blocks resident) ----------------
__device__ volatile unsigned g_gen;     // generation ticket (persists across launches)
__device__ unsigned          g_count;

__device__ __forceinline__ void gsync(unsigned gen0, unsigned k) {
    __syncthreads();
    if (threadIdx.x == 0) {
        __threadfence();
        if (atomicAdd(&g_count, 1u) == NB - 1u) {
            g_count = 0u;
            __threadfence();
            g_gen = gen0 + k;                 // release
        } else {
            while (g_gen != gen0 + k) { __nanosleep(64); }
        }
        __threadfence();
    }
    __syncthreads();
}

// ---------------- f32x2 packed FMA helpers (Blackwell) -----------------------
__device__ __forceinline__ void ffma2(unsigned long long& d,
                                      unsigned long long a, unsigned long long b) {
    asm("fma.rn.f32x2 %0, %1, %2, %0;" : "+l"(d) : "l"(a), "l"(b));
}
__device__ __forceinline__ unsigned long long pack2(float lo, float hi) {
    unsigned long long r;
    asm("mov.b64 %0, {%1, %2};" : "=l"(r) : "f"(lo), "f"(hi));
    return r;
}
__device__ __forceinline__ float unpack_sum(unsigned long long v) {
    float lo, hi;
    asm("mov.b64 {%0, %1}, %2;" : "=f"(lo), "=f"(hi) : "l"(v));
    return lo + hi;
}

// inclusive scan of one value per thread across 1024 threads (single block)
__device__ __forceinline__ int scan1(int v, int t, int* s) {
    s[t] = v;
    __syncthreads();
#pragma unroll
    for (int off = 1; off < NT; off <<= 1) {
        int u = (t >= off) ? s[t - off] : 0;
        __syncthreads();
        s[t] += u;
        __syncthreads();
    }
    int r = s[t];
    __syncthreads();
    return r;
}

__device__ __forceinline__ void compact_flags(const int* flags, int* list, int* cnt_out,
                                              int t, int* s) {
    int f = flags[t];
    int incl = scan1(f, t, s);
    if (f) list[incl - 1] = t;
    if (t == NT - 1) *cnt_out = incl;
}

__global__ __launch_bounds__(NT) void k_mega(
    const float* __restrict__ x, const void* __restrict__ eidx,
    const float* __restrict__ W_emb,  const float* __restrict__ b_emb,
    const float* __restrict__ W_conv, const float* __restrict__ b_conv,
    const float* __restrict__ W_cls,  const float* __restrict__ b_cls,
    float* __restrict__ out)
{
    __shared__ __align__(16) float sm[8192];     // 32 KB, unioned across phases
    const int t   = threadIdx.x;
    const int bid = blockIdx.x;
    const unsigned gen0 = g_gen;                 // stable: prior launch fully done

    // ======== P0: embedding (blocks 0..15, 4 batches each)
    //          || edge convert + deg + flag3 (blocks 16..31)
    if (bid < 16) {
        int b0 = bid * 4;
        float* xs   = sm;             // [4][1024]
        float* part = sm + 4096;      // [4][8][128]
        float* h0   = sm;             // [4][128]  (reuses xs after consumption)
#pragma unroll
        for (int bb = 0; bb < 4; bb++) xs[bb * 1024 + t] = x[(b0 + bb) * D_ + t];
        __syncthreads();
        int c = t & 127, ds = t >> 7;             // 8 d-slices of 128
        int d0 = ds * 128;
        float a0 = 0.f, a1 = 0.f, a2 = 0.f, a3 = 0.f;
#pragma unroll 4
        for (int d = d0; d < d0 + 128; d++) {
            float w = W_emb[d * C_ + c];
            a0 += xs[d] * w;
            a1 += xs[1024 + d] * w;
            a2 += xs[2048 + d] * w;
            a3 += xs[3072 + d] * w;
        }
        part[0 * 1024 + ds * 128 + c] = a0;
        part[1 * 1024 + ds * 128 + c] = a1;
        part[2 * 1024 + ds * 128 + c] = a2;
        part[3 * 1024 + ds * 128 + c] = a3;
        __syncthreads();
        if (t < 512) {
            int bb = t >> 7, cc = t & 127;
            float h = b_emb[cc];
#pragma unroll
            for (int s = 0; s < 8; s++) h += part[bb * 1024 + s * 128 + cc];
            h0[bb * 128 + cc] = fmaxf(h, 0.f);
        }
        __syncthreads();
        // w0[b] = h0[b] @ W_conv, split over 8 k-slices of 16
        int k0 = ds * 16;
        float p0 = 0.f, p1 = 0.f, p2 = 0.f, p3 = 0.f;
#pragma unroll
        for (int k = k0; k < k0 + 16; k++) {
            float w = W_conv[k * C_ + c];
            p0 += h0[0 * 128 + k] * w;
            p1 += h0[1 * 128 + k] * w;
            p2 += h0[2 * 128 + k] * w;
            p3 += h0[3 * 128 + k] * w;
        }
        __syncthreads();              // h0 reads done before part overwrite? part != h0; safe, but keep order
        part[0 * 1024 + ds * 128 + c] = p0;
        part[1 * 1024 + ds * 128 + c] = p1;
        part[2 * 1024 + ds * 128 + c] = p2;
        part[3 * 1024 + ds * 128 + c] = p3;
        __syncthreads();
        if (t < 512) {
            int bb = t >> 7, cc = t & 127;
            float a = 0.f;
#pragma unroll
            for (int s = 0; s < 8; s++) a += part[bb * 1024 + s * 128 + cc];
            g_w0[(b0 + bb) * C_ + cc] = a;
        }
    } else if (bid < 32) {
        int e = (bid - 16) * 1024 + t;            // 16*1024 == E_
        const unsigned* ew32 = (const unsigned*)eidx;
        int any = __syncthreads_or(ew32[2 * e + 1] != 0u);
        int is64 = !any;                          // int64 => high words all zero
        int s, d;
        if (is64) {
            const long long* p = (const long long*)eidx;
            s = (int)p[e]; d = (int)p[E_ + e];
        } else {
            const int* p = (const int*)eidx;
            s = p[e]; d = p[E_ + e];
        }
        g_src[e] = s; g_dst[e] = d;
        atomicAdd(&g_deg[d], 1);                  // deg/flag3 pre-cleared (end of prev launch)
        if (d == 0) g_flag3[s] = 1;
    }
    gsync(gen0, 1);

    // ======== P1: flag2 (blocks 0..15) || degf+rowptr scan (16) || flag3 compact (17)
    if (bid < 16) {
        int e = bid * 1024 + t;
        if (g_flag3[g_dst[e]]) g_flag2[g_src[e]] = 1;
    } else if (bid == 16) {
        int d = g_deg[t];
        g_degf[t] = (float)d;
        int incl = scan1(d, t, (int*)sm);
        g_rowptr[t + 1] = incl;
        if (t == 0) g_rowptr[0] = 0;
    } else if (bid == 17) {
        compact_flags(g_flag3, g_list3, &g_c3, t, (int*)sm);
    }
    gsync(gen0, 2);

    // ======== P2: csrfill + nbrdeg (blocks 0..130, 4 warps/node, int4 loads)
    //          || flag2 compact (131)
    if (bid == 131) {
        compact_flags(g_flag2, g_list2, &g_c2, t, (int*)sm);
    } else {
        int grp  = t >> 7;                        // 8 node-groups per block
        int w    = (t >> 5) & 3;                  // warp within group (quarter of edges)
        int lane = t & 31;
        int n    = bid * 8 + grp;                 // 0..1047
        int* cnts = (int*)sm;                     // [8][4]
        bool act = (n < N_) && (g_flag2[n] | g_flag3[n] | (n == 0));
        int e0 = w * (E_ / 4);
        if (act) {
            // pass 1: count my quarter
            int tot = 0;
#pragma unroll 4
            for (int m = 0; m < 32; m++) {
                const int4 d4 = *(const int4*)&g_dst[e0 + m * 128 + lane * 4];
                tot += (d4.x == n) + (d4.y == n) + (d4.z == n) + (d4.w == n);
            }
#pragma unroll
            for (int off = 16; off > 0; off >>= 1)
                tot += __shfl_xor_sync(FULLM, tot, off);
            if (lane == 0) cnts[grp * 4 + w] = tot;
        }
        __syncthreads();
        if (act) {
            int base = g_rowptr[n];
            for (int j = 0; j < w; j++) base += cnts[grp * 4 + j];
            int run = 0;
            // pass 2: stable placement (edge order preserved: index = 4*lane+j)
            for (int m = 0; m < 32; m++) {
                int eb = e0 + m * 128 + lane * 4;
                const int4 d4 = *(const int4*)&g_dst[eb];
                const int4 s4 = *(const int4*)&g_src[eb];
                int m0 = (d4.x == n), m1 = (d4.y == n), m2 = (d4.z == n), m3 = (d4.w == n);
                int cnt = m0 + m1 + m2 + m3;
                int inc = cnt;
#pragma unroll
                for (int off = 1; off < 32; off <<= 1) {
                    int v = __shfl_up_sync(FULLM, inc, off);
                    if (lane >= off) inc += v;
                }
                int pos = base + run + inc - cnt;
                if (m0) { g_col[pos] = s4.x; g_nbrdeg[pos] = g_degf[s4.x]; pos++; }
                if (m1) { g_col[pos] = s4.y; g_nbrdeg[pos] = g_degf[s4.y]; pos++; }
                if (m2) { g_col[pos] = s4.z; g_nbrdeg[pos] = g_degf[s4.z]; pos++; }
                if (m3) { g_col[pos] = s4.w; g_nbrdeg[pos] = g_degf[s4.w]; pos++; }
                run += __shfl_sync(FULLM, inc, 31);
            }
        }
    }
    gsync(gen0, 3);

    // ======== P3: conv2 fused agg (analytic conv1) + f32x2 GEMM + relu ========
    {
        int cnt2 = g_c2;
        int M = B_ * cnt2;
        int ntiles = (M + 63) >> 6;
        int c = t & 127, rg = t >> 7;             // 8 row-groups x 8 rows
        float bc = b_conv[c];
        float (*As)[C_] = (float (*)[C_])sm;      // [64][128]
        for (int tile = bid; tile < ntiles; tile += NB) {
            int r0 = tile * 64;
            for (int r = rg * 8; r < rg * 8 + 8; r++) {
                int rr = r0 + r;
                float acc = 0.f;
                if (rr < M) {
                    int b = rr / cnt2, i = rr - b * cnt2;
                    int n = g_list2[i];
                    int s0 = g_rowptr[n], s1 = g_rowptr[n + 1];
                    float wb = g_w0[b * C_ + c];
#pragma unroll 4
                    for (int q = s0; q < s1; q++)
                        acc += fmaxf(g_nbrdeg[q] * wb + bc, 0.f);
                }
                As[r][c] = acc;
            }
            __syncthreads();
            unsigned long long acc2[8];
#pragma unroll
            for (int r = 0; r < 8; r++) acc2[r] = 0ull;      // two packed +0.0f
#pragma unroll 4
            for (int k = 0; k < C_; k += 4) {
                unsigned long long w01 = pack2(W_conv[(k + 0) * C_ + c],
                                               W_conv[(k + 1) * C_ + c]);
                unsigned long long w23 = pack2(W_conv[(k + 2) * C_ + c],
                                               W_conv[(k + 3) * C_ + c]);
#pragma unroll
                for (int r = 0; r < 8; r++) {
                    const ulonglong2 av = *(const ulonglong2*)&As[rg * 8 + r][k];
                    ffma2(acc2[r], av.x, w01);
                    ffma2(acc2[r], av.y, w23);
                }
            }
            for (int r = 0; r < 8; r++) {
                int rr = r0 + rg * 8 + r;
                if (rr < M) {
                    int b = rr / cnt2, i = rr - b * cnt2;
                    g_H2[(b * N_ + g_list2[i]) * C_ + c] =
                        fmaxf(unpack_sum(acc2[r]) + bc, 0.f);
                }
            }
            __syncthreads();
        }
    }
    gsync(gen0, 4);

    // ======== P4: conv3 fused agg + f32x2 GEMM + relu =========================
    {
        int cnt3 = g_c3;
        int M = B_ * cnt3;
        int ntiles = (M + 63) >> 6;
        int c = t & 127, rg = t >> 7;
        float bc = b_conv[c];
        float (*As)[C_] = (float (*)[C_])sm;
        for (int tile = bid; tile < ntiles; tile += NB) {
            int r0 = tile * 64;
            for (int r = rg * 8; r < rg * 8 + 8; r++) {
                int rr = r0 + r;
                float acc = 0.f;
                if (rr < M) {
                    int b = rr / cnt3, i = rr - b * cnt3;
                    int n = g_list3[i];
                    int s0 = g_rowptr[n], s1 = g_rowptr[n + 1];
#pragma unroll 4
                    for (int q = s0; q < s1; q++)
                        acc += g_H2[(b * N_ + g_col[q]) * C_ + c];
                }
                As[r][c] = acc;
            }
            __syncthreads();
            unsigned long long acc2[8];
#pragma unroll
            for (int r = 0; r < 8; r++) acc2[r] = 0ull;
#pragma unroll 4
            for (int k = 0; k < C_; k += 4) {
                unsigned long long w01 = pack2(W_conv[(k + 0) * C_ + c],
                                               W_conv[(k + 1) * C_ + c]);
                unsigned long long w23 = pack2(W_conv[(k + 2) * C_ + c],
                                               W_conv[(k + 3) * C_ + c]);
#pragma unroll
                for (int r = 0; r < 8; r++) {
                    const ulonglong2 av = *(const ulonglong2*)&As[rg * 8 + r][k];
                    ffma2(acc2[r], av.x, w01);
                    ffma2(acc2[r], av.y, w23);
                }
            }
            for (int r = 0; r < 8; r++) {
                int rr = r0 + rg * 8 + r;
                if (rr < M) {
                    int b = rr / cnt3, i = rr - b * cnt3;
                    g_H3[(b * N_ + g_list3[i]) * C_ + c] =
                        fmaxf(unpack_sum(acc2[r]) + bc, 0.f);
                }
            }
            __syncthreads();
        }
    }
    gsync(gen0, 5);

    // ======== P5: conv4 agg (node 0) + GEMM + classifier (blocks 0..63)
    //          || clear scratch for next launch (blocks 64..66)
    if (bid < B_) {
        float* s4  = sm;        // [128]
        float* red = sm + C_;   // [128]
        if (t < C_) {
            int s0 = g_rowptr[0], s1 = g_rowptr[1];
            float acc = 0.f;
#pragma unroll 4
            for (int q = s0; q < s1; q++)
                acc += g_H3[(bid * N_ + g_col[q]) * C_ + t];
            s4[t] = acc;
        }
        __syncthreads();
        if (t < C_) {
            float a2 = b_conv[t];
#pragma unroll 8
            for (int k = 0; k < C_; k++) a2 += s4[k] * W_conv[k * C_ + t];
            red[t] = fmaxf(a2, 0.f) * W_cls[t];
        }
        __syncthreads();
#pragma unroll
        for (int off = 64; off > 0; off >>= 1) {
            if (t < off) red[t] += red[t + off];
            __syncthreads();
        }
        if (t == 0) out[bid] = red[0] + b_cls[0];
    } else if (bid == 64) {
        g_deg[t] = 0;
    } else if (bid == 65) {
        g_flag2[t] = 0;
    } else if (bid == 66) {
        g_flag3[t] = 0;
    }
}

extern "C" void kernel_launch(void* const* d_in, const int* in_sizes, int n_in,
                              void* d_out, int out_size) {
    (void)in_sizes; (void)n_in; (void)out_size;
    const float* x      = (const float*)d_in[0];
    const void*  eidx   = d_in[1];
    const float* W_emb  = (const float*)d_in[2];
    const float* b_emb  = (const float*)d_in[3];
    const float* W_conv = (const float*)d_in[4];
    const float* b_conv = (const float*)d_in[5];
    const float* W_cls  = (const float*)d_in[6];
    const float* b_cls  = (const float*)d_in[7];
    float* out = (float*)d_out;

    k_mega<<<NB, NT>>>(x, eidx, W_emb, b_emb, W_conv, b_conv, W_cls, b_cls, out);
}

// round 9
// speedup vs baseline: 2.6909x; 1.1899x over previous
#include <cuda_runtime.h>
#include <cuda_bf16.h>

// Problem constants (fixed by setup_inputs)
#define B_ 64
#define N_ 1024
#define E_ 16384
#define D_ 1024
#define C_ 128

#define NB 132          // 1 block per SM (<=148) -> co-residency guaranteed
#define NT 1024
#define FULLM 0xffffffffu
#define DMAXP1 (E_ + 1) // degree value range bound

// ---------------- device scratch (static, no allocations) ----------------
// deg/flag2/flag3/flagd/nd are cleared at the END of each launch (zero-init at load).
__device__ __align__(16) int g_src[E_];
__device__ __align__(16) int g_dst[E_];
__device__ int   g_deg[N_];
__device__ int   g_rowptr[N_ + 1];
__device__ int   g_col[E_];
__device__ int   g_nbrrank[E_];         // degree-rank of neighbor, per CSR slot
__device__ int   g_flag2[N_], g_flag3[N_];
__device__ int   g_list2[N_], g_list3[N_];
__device__ int   g_c2, g_c3;
__device__ int   g_flagd[DMAXP1];       // degree-value claimed flags
__device__ int   g_degrank[DMAXP1];     // degree value -> rank
__device__ float g_dval[N_];            // rank -> degree value (as float)
__device__ int   g_nd;                  // number of distinct degree values
__device__ float g_w0[B_ * C_];         // (h0 @ W_conv) per batch
__device__ float g_G[N_ * B_ * C_];     // G[rank][b][c] = H1row(deg) @ W_conv
__device__ float g_H2[B_ * N_ * C_];    // node-indexed (frontier2 rows valid)
__device__ float g_H3[B_ * N_ * C_];    // node-indexed (frontier3 rows valid)

// ---------------- software grid barrier (all blocks resident) ----------------
__device__ volatile unsigned g_gen;
__device__ unsigned          g_count;

__device__ __forceinline__ void gsync(unsigned gen0, unsigned k) {
    __syncthreads();
    if (threadIdx.x == 0) {
        __threadfence();
        if (atomicAdd(&g_count, 1u) == NB - 1u) {
            g_count = 0u;
            __threadfence();
            g_gen = gen0 + k;
        } else {
            while (g_gen != gen0 + k) { __nanosleep(64); }
        }
        __threadfence();
    }
    __syncthreads();
}

// ---------------- f32x2 packed FMA helpers (Blackwell) -----------------------
__device__ __forceinline__ void ffma2(unsigned long long& d,
                                      unsigned long long a, unsigned long long b) {
    asm("fma.rn.f32x2 %0, %1, %2, %0;" : "+l"(d) : "l"(a), "l"(b));
}
__device__ __forceinline__ unsigned long long pack2(float lo, float hi) {
    unsigned long long r;
    asm("mov.b64 %0, {%1, %2};" : "=l"(r) : "f"(lo), "f"(hi));
    return r;
}
__device__ __forceinline__ float unpack_sum(unsigned long long v) {
    float lo, hi;
    asm("mov.b64 {%0, %1}, %2;" : "=f"(lo), "=f"(hi) : "l"(v));
    return lo + hi;
}

// inclusive scan of one value per thread across 1024 threads (single block)
__device__ __forceinline__ int scan1(int v, int t, int* s) {
    s[t] = v;
    __syncthreads();
#pragma unroll
    for (int off = 1; off < NT; off <<= 1) {
        int u = (t >= off) ? s[t - off] : 0;
        __syncthreads();
        s[t] += u;
        __syncthreads();
    }
    int r = s[t];
    __syncthreads();
    return r;
}

__device__ __forceinline__ void compact_flags(const int* flags, int* list, int* cnt_out,
                                              int t, int* s) {
    int f = flags[t];
    int incl = scan1(f, t, s);
    if (f) list[incl - 1] = t;
    if (t == NT - 1) *cnt_out = incl;
}

__global__ __launch_bounds__(NT) void k_mega(
    const float* __restrict__ x, const void* __restrict__ eidx,
    const float* __restrict__ W_emb,  const float* __restrict__ b_emb,
    const float* __restrict__ W_conv, const float* __restrict__ b_conv,
    const float* __restrict__ W_cls,  const float* __restrict__ b_cls,
    float* __restrict__ out)
{
    __shared__ __align__(16) float sm[8192];     // 32 KB, unioned across phases
    const int t   = threadIdx.x;
    const int bid = blockIdx.x;
    const unsigned gen0 = g_gen;

    // ======== P0: embedding (blocks 0..31, 2 batches each)
    //          || edge convert + deg + flag3 (blocks 32..47)
    if (bid < 32) {
        int b0 = bid * 2;
        float* xs   = sm;             // [2][1024]
        float* part = sm + 2048;      // [2][8][128]
        float* h0   = sm + 4096;      // [2][128]
        xs[t] = x[b0 * D_ + t];
        xs[1024 + t] = x[(b0 + 1) * D_ + t];
        __syncthreads();
        int c = t & 127, ds = t >> 7;             // 8 d-slices of 128
        int d0 = ds * 128;
        float a0 = 0.f, a1 = 0.f;
#pragma unroll 8
        for (int d = d0; d < d0 + 128; d++) {
            float w = W_emb[d * C_ + c];
            a0 += xs[d] * w;
            a1 += xs[1024 + d] * w;
        }
        part[ds * 128 + c] = a0;
        part[1024 + ds * 128 + c] = a1;
        __syncthreads();
        if (t < 256) {
            int bb = t >> 7, cc = t & 127;
            float h = b_emb[cc];
#pragma unroll
            for (int s = 0; s < 8; s++) h += part[bb * 1024 + s * 128 + cc];
            h0[bb * 128 + cc] = fmaxf(h, 0.f);
        }
        __syncthreads();
        int k0 = ds * 16;
        float p0 = 0.f, p1 = 0.f;
#pragma unroll
        for (int k = k0; k < k0 + 16; k++) {
            float w = W_conv[k * C_ + c];
            p0 += h0[k] * w;
            p1 += h0[128 + k] * w;
        }
        __syncthreads();
        part[ds * 128 + c] = p0;
        part[1024 + ds * 128 + c] = p1;
        __syncthreads();
        if (t < 256) {
            int bb = t >> 7, cc = t & 127;
            float a = 0.f;
#pragma unroll
            for (int s = 0; s < 8; s++) a += part[bb * 1024 + s * 128 + cc];
            g_w0[(b0 + bb) * C_ + cc] = a;
        }
    } else if (bid < 48) {
        int e = (bid - 32) * 1024 + t;            // 16*1024 == E_
        const unsigned* ew32 = (const unsigned*)eidx;
        int any = __syncthreads_or(ew32[2 * e + 1] != 0u);
        int is64 = !any;                          // int64 => high words all zero
        int s, d;
        if (is64) {
            const long long* p = (const long long*)eidx;
            s = (int)p[e]; d = (int)p[E_ + e];
        } else {
            const int* p = (const int*)eidx;
            s = p[e]; d = p[E_ + e];
        }
        g_src[e] = s; g_dst[e] = d;
        atomicAdd(&g_deg[d], 1);
        if (d == 0) g_flag3[s] = 1;
    }
    gsync(gen0, 1);

    // ======== P1: flag2 (0..15) || rowptr scan (16) || flag3 compact (17)
    //          || degree-rank claim (18)
    if (bid < 16) {
        int e = bid * 1024 + t;
        if (g_flag3[g_dst[e]]) g_flag2[g_src[e]] = 1;
    } else if (bid == 16) {
        int d = g_deg[t];
        int incl = scan1(d, t, (int*)sm);
        g_rowptr[t + 1] = incl;
        if (t == 0) g_rowptr[0] = 0;
    } else if (bid == 17) {
        compact_flags(g_flag3, g_list3, &g_c3, t, (int*)sm);
    } else if (bid == 18) {
        int d = g_deg[t];                          // thread t handles node t
        int old = atomicExch(&g_flagd[d], 1);
        if (old == 0) {
            int r = atomicAdd(&g_nd, 1);
            g_degrank[d] = r;
            g_dval[r] = (float)d;
        }
    }
    gsync(gen0, 2);

    // ======== P2: csrfill (blocks 0..63, 16 nodes/block, 2 warps/node)
    //          || G-table build (blocks 64..130) || flag2 compact (131)
    if (bid < 64) {
        int grp  = t >> 6;                        // 16 node-groups
        int w    = (t >> 5) & 1;                  // warp within group (half of edges)
        int lane = t & 31;
        int n    = bid * 16 + grp;
        int* s_it = (int*)sm;                     // [16][2][64] iteration totals
        bool act = (g_flag2[n] | g_flag3[n] | (n == 0));
        int e0 = w * (E_ / 2);
        if (act) {
            for (int m = 0; m < 64; m++) {
                const int4 d4 = *(const int4*)&g_dst[e0 + m * 128 + lane * 4];
                int tot = (d4.x == n) + (d4.y == n) + (d4.z == n) + (d4.w == n);
#pragma unroll
                for (int off = 16; off > 0; off >>= 1)
                    tot += __shfl_xor_sync(FULLM, tot, off);
                if (lane == 0) s_it[(grp * 2 + w) * 64 + m] = tot;
            }
        }
        __syncthreads();
        if (act) {
            // exclusive prefix of my warp's 64 iteration totals (lane m holds iters m, m+32)
            int a  = s_it[(grp * 2 + w) * 64 + lane];
            int bq = s_it[(grp * 2 + w) * 64 + 32 + lane];
            int incA = a, incB = bq;
#pragma unroll
            for (int off = 1; off < 32; off <<= 1) {
                int v = __shfl_up_sync(FULLM, incA, off); if (lane >= off) incA += v;
                int u = __shfl_up_sync(FULLM, incB, off); if (lane >= off) incB += u;
            }
            int totA  = __shfl_sync(FULLM, incA, 31);
            int runLo = incA - a;
            int runHi = totA + incB - bq;
            int base = g_rowptr[n];
            if (w == 1) {
                int s0 = s_it[(grp * 2) * 64 + lane] + s_it[(grp * 2) * 64 + 32 + lane];
#pragma unroll
                for (int off = 16; off > 0; off >>= 1)
                    s0 += __shfl_xor_sync(FULLM, s0, off);
                base += s0;
            }
            unsigned lt = (1u << lane) - 1u;
            for (int m = 0; m < 64; m++) {
                int eb = e0 + m * 128 + lane * 4;
                const int4 d4 = *(const int4*)&g_dst[eb];
                const int4 s4 = *(const int4*)&g_src[eb];
                int m0 = (d4.x == n), m1 = (d4.y == n), m2 = (d4.z == n), m3 = (d4.w == n);
                unsigned bl0 = __ballot_sync(FULLM, m0), bl1 = __ballot_sync(FULLM, m1);
                unsigned bl2 = __ballot_sync(FULLM, m2), bl3 = __ballot_sync(FULLM, m3);
                int run_m = (m < 32) ? __shfl_sync(FULLM, runLo, m)
                                     : __shfl_sync(FULLM, runHi, m - 32);
                int pos = base + run_m +
                          __popc(bl0 & lt) + __popc(bl1 & lt) +
                          __popc(bl2 & lt) + __popc(bl3 & lt);
                if (m0) { g_col[pos] = s4.x; g_nbrrank[pos] = g_degrank[g_deg[s4.x]]; pos++; }
                if (m1) { g_col[pos] = s4.y; g_nbrrank[pos] = g_degrank[g_deg[s4.y]]; pos++; }
                if (m2) { g_col[pos] = s4.z; g_nbrrank[pos] = g_degrank[g_deg[s4.z]]; pos++; }
                if (m3) { g_col[pos] = s4.w; g_nbrrank[pos] = g_degrank[g_deg[s4.w]]; }
            }
        }
    } else if (bid < 131) {
        // G[rank][b][:] = relu(dval*w0[b]+bc) @ W_conv  (one 64-row tile per rank)
        int nd = g_nd;
        int c = t & 127, rg = t >> 7;
        float bc = b_conv[c];
        float (*As)[C_] = (float (*)[C_])sm;      // [64][128], row r == batch b
        for (int rank = bid - 64; rank < nd; rank += 67) {
            float dv = g_dval[rank];
            for (int r = rg * 8; r < rg * 8 + 8; r++)
                As[r][c] = fmaxf(dv * g_w0[r * C_ + c] + bc, 0.f);
            __syncthreads();
            unsigned long long acc2[8];
#pragma unroll
            for (int r = 0; r < 8; r++) acc2[r] = 0ull;
#pragma unroll 4
            for (int k = 0; k < C_; k += 4) {
                unsigned long long w01 = pack2(W_conv[(k + 0) * C_ + c],
                                               W_conv[(k + 1) * C_ + c]);
                unsigned long long w23 = pack2(W_conv[(k + 2) * C_ + c],
                                               W_conv[(k + 3) * C_ + c]);
#pragma unroll
                for (int r = 0; r < 8; r++) {
                    const ulonglong2 av = *(const ulonglong2*)&As[rg * 8 + r][k];
                    ffma2(acc2[r], av.x, w01);
                    ffma2(acc2[r], av.y, w23);
                }
            }
#pragma unroll
            for (int r = 0; r < 8; r++)
                g_G[(rank * B_ + rg * 8 + r) * C_ + c] = unpack_sum(acc2[r]);
            __syncthreads();
        }
    } else {
        compact_flags(g_flag2, g_list2, &g_c2, t, (int*)sm);
    }
    gsync(gen0, 3);

    // ======== P3: conv2 = aggregation of G rows (CSR order) + bias + relu =====
    {
        int cnt2 = g_c2;
        int M2 = B_ * cnt2;
        int gidx = bid * 8 + (t >> 7);
        int c = t & 127;
        float bc = b_conv[c];
        for (int row = gidx; row < M2; row += NB * 8) {
            int b = row / cnt2, i = row - b * cnt2;
            int n = g_list2[i];
            int s0 = g_rowptr[n], s1 = g_rowptr[n + 1];
            float acc = 0.f;
#pragma unroll 4
            for (int q = s0; q < s1; q++)
                acc += g_G[(g_nbrrank[q] * B_ + b) * C_ + c];
            g_H2[(b * N_ + n) * C_ + c] = fmaxf(acc + bc, 0.f);
        }
    }
    gsync(gen0, 4);

    // ======== P4: conv3 fused agg + f32x2 GEMM + relu (8-row tile per group) ==
    {
        int cnt3 = g_c3;
        int M3 = B_ * cnt3;
        int ntiles = (M3 + 7) >> 3;
        int trips = (ntiles + NB * 8 - 1) / (NB * 8);
        int grp = t >> 7, c = t & 127;
        float bc = b_conv[c];
        float (*As)[C_] = (float (*)[C_])sm;      // [64][128], group grp owns rows grp*8..+7
        for (int tr = 0; tr < trips; tr++) {
            int tile = tr * NB * 8 + bid * 8 + grp;
            for (int r = 0; r < 8; r++) {
                int rr = tile * 8 + r;
                float acc = 0.f;
                if (tile < ntiles && rr < M3) {
                    int b = rr / cnt3, i = rr - b * cnt3;
                    int n = g_list3[i];
                    int s0 = g_rowptr[n], s1 = g_rowptr[n + 1];
#pragma unroll 8
                    for (int q = s0; q < s1; q++)
                        acc += g_H2[(b * N_ + g_col[q]) * C_ + c];
                }
                As[grp * 8 + r][c] = acc;
            }
            __syncthreads();
            unsigned long long acc2[8];
#pragma unroll
            for (int r = 0; r < 8; r++) acc2[r] = 0ull;
#pragma unroll 4
            for (int k = 0; k < C_; k += 4) {
                unsigned long long w01 = pack2(W_conv[(k + 0) * C_ + c],
                                               W_conv[(k + 1) * C_ + c]);
                unsigned long long w23 = pack2(W_conv[(k + 2) * C_ + c],
                                               W_conv[(k + 3) * C_ + c]);
#pragma unroll
                for (int r = 0; r < 8; r++) {
                    const ulonglong2 av = *(const ulonglong2*)&As[grp * 8 + r][k];
                    ffma2(acc2[r], av.x, w01);
                    ffma2(acc2[r], av.y, w23);
                }
            }
            for (int r = 0; r < 8; r++) {
                int rr = tile * 8 + r;
                if (tile < ntiles && rr < M3) {
                    int b = rr / cnt3, i = rr - b * cnt3;
                    g_H3[(b * N_ + g_list3[i]) * C_ + c] =
                        fmaxf(unpack_sum(acc2[r]) + bc, 0.f);
                }
            }
            __syncthreads();
        }
    }
    gsync(gen0, 5);

    // ======== P5: conv4 agg (node 0) + GEMM + classifier (blocks 0..63)
    //          || clear scratch for next launch (blocks 64..67)
    if (bid < B_) {
        float* s4  = sm;        // [128]
        float* red = sm + C_;   // [128]
        if (t < C_) {
            int s0 = g_rowptr[0], s1 = g_rowptr[1];
            float acc = 0.f;
#pragma unroll 4
            for (int q = s0; q < s1; q++)
                acc += g_H3[(bid * N_ + g_col[q]) * C_ + t];
            s4[t] = acc;
        }
        __syncthreads();
        if (t < C_) {
            float a2 = b_conv[t];
#pragma unroll 8
            for (int k = 0; k < C_; k++) a2 += s4[k] * W_conv[k * C_ + t];
            red[t] = fmaxf(a2, 0.f) * W_cls[t];
        }
        __syncthreads();
#pragma unroll
        for (int off = 64; off > 0; off >>= 1) {
            if (t < off) red[t] += red[t + off];
            __syncthreads();
        }
        if (t == 0) out[bid] = red[0] + b_cls[0];
    } else if (bid == 64) {
        g_deg[t] = 0;
    } else if (bid == 65) {
        g_flag2[t] = 0;
    } else if (bid == 66) {
        g_flag3[t] = 0;
    } else if (bid == 67) {
        int nd = g_nd;
        if (t < nd) g_flagd[(int)g_dval[t]] = 0;
        __syncthreads();
        if (t == 0) g_nd = 0;
    }
}

extern "C" void kernel_launch(void* const* d_in, const int* in_sizes, int n_in,
                              void* d_out, int out_size) {
    (void)in_sizes; (void)n_in; (void)out_size;
    const float* x      = (const float*)d_in[0];
    const void*  eidx   = d_in[1];
    const float* W_emb  = (const float*)d_in[2];
    const float* b_emb  = (const float*)d_in[3];
    const float* W_conv = (const float*)d_in[4];
    const float* b_conv = (const float*)d_in[5];
    const float* W_cls  = (const float*)d_in[6];
    const float* b_cls  = (const float*)d_in[7];
    float* out = (float*)d_out;

    k_mega<<<NB, NT>>>(x, eidx, W_emb, b_emb, W_conv, b_conv, W_cls, b_cls, out);
}

// round 10
// speedup vs baseline: 4.2479x; 1.5786x over previous
#include <cuda_runtime.h>
#include <cuda_bf16.h>

// Problem constants (fixed by setup_inputs)
#define B_ 64
#define N_ 1024
#define E_ 16384
#define D_ 1024
#define C_ 128

#define NB 132          // 1 block per SM (<=148) -> co-residency guaranteed
#define NT 1024
#define FULLM 0xffffffffu
#define DMAXP1 (E_ + 1) // degree value range bound

// ---------------- device scratch (static, no allocations) ----------------
// deg/flag2/flag3/flagd/nd are cleared at the END of each launch (zero-init at load).
__device__ __align__(16) int g_src[E_];
__device__ __align__(16) int g_dst[E_];
__device__ int   g_deg[N_];
__device__ int   g_nrank[N_];           // node -> degree-rank
__device__ int   g_rowptr[N_ + 1];
__device__ int   g_col[E_];
__device__ int   g_nbrrank[E_];         // degree-rank of neighbor, per CSR slot
__device__ int   g_flag2[N_], g_flag3[N_];
__device__ int   g_list2[N_], g_list3[N_];
__device__ int   g_c2, g_c3;
__device__ int   g_flagd[DMAXP1];       // degree-value claimed flags
__device__ int   g_degrank[DMAXP1];     // degree value -> rank
__device__ float g_dval[N_];            // rank -> degree value (as float)
__device__ int   g_nd;                  // number of distinct degree values
__device__ float g_w0[B_ * C_];         // (h0 @ W_conv) per batch
__device__ float g_G[N_ * B_ * C_];     // G[rank][b][c] = H1row(deg) @ W_conv
__device__ float g_H2[B_ * N_ * C_];    // node-indexed (frontier2 rows valid)
__device__ float g_H3[B_ * N_ * C_];    // node-indexed (frontier3 rows valid)

// ---------------- software grid barrier (all blocks resident) ----------------
__device__ volatile unsigned g_gen;
__device__ unsigned          g_count;

__device__ __forceinline__ void gsync(unsigned gen0, unsigned k) {
    __syncthreads();
    if (threadIdx.x == 0) {
        __threadfence();
        if (atomicAdd(&g_count, 1u) == NB - 1u) {
            g_count = 0u;
            __threadfence();
            g_gen = gen0 + k;
        } else {
            while (g_gen != gen0 + k) { __nanosleep(64); }
        }
        __threadfence();
    }
    __syncthreads();
}

// ---------------- f32x2 packed FMA helpers (Blackwell) -----------------------
__device__ __forceinline__ void ffma2(unsigned long long& d,
                                      unsigned long long a, unsigned long long b) {
    asm("fma.rn.f32x2 %0, %1, %2, %0;" : "+l"(d) : "l"(a), "l"(b));
}
__device__ __forceinline__ unsigned long long pack2(float lo, float hi) {
    unsigned long long r;
    asm("mov.b64 %0, {%1, %2};" : "=l"(r) : "f"(lo), "f"(hi));
    return r;
}
__device__ __forceinline__ float unpack_sum(unsigned long long v) {
    float lo, hi;
    asm("mov.b64 {%0, %1}, %2;" : "=f"(lo), "=f"(hi) : "l"(v));
    return lo + hi;
}

// inclusive scan of one value per thread across 1024 threads (single block)
__device__ __forceinline__ int scan1(int v, int t, int* s) {
    s[t] = v;
    __syncthreads();
#pragma unroll
    for (int off = 1; off < NT; off <<= 1) {
        int u = (t >= off) ? s[t - off] : 0;
        __syncthreads();
        s[t] += u;
        __syncthreads();
    }
    int r = s[t];
    __syncthreads();
    return r;
}

__device__ __forceinline__ void compact_flags(const int* flags, int* list, int* cnt_out,
                                              int t, int* s) {
    int f = flags[t];
    int incl = scan1(f, t, s);
    if (f) list[incl - 1] = t;
    if (t == NT - 1) *cnt_out = incl;
}

__global__ __launch_bounds__(NT) void k_mega(
    const float* __restrict__ x, const void* __restrict__ eidx,
    const float* __restrict__ W_emb,  const float* __restrict__ b_emb,
    const float* __restrict__ W_conv, const float* __restrict__ b_conv,
    const float* __restrict__ W_cls,  const float* __restrict__ b_cls,
    float* __restrict__ out)
{
    __shared__ __align__(16) float sm[8192];     // 32 KB, unioned across phases
    const int t   = threadIdx.x;
    const int bid = blockIdx.x;
    const unsigned gen0 = g_gen;

    // ======== P0: embedding (blocks 0..31, 2 batches each)
    //          || edge convert + deg + flag3 (blocks 32..47)
    if (bid < 32) {
        int b0 = bid * 2;
        float* xs   = sm;             // [2][1024]
        float* part = sm + 2048;      // [2][8][128]
        float* h0   = sm + 4096;      // [2][128]
        xs[t] = x[b0 * D_ + t];
        xs[1024 + t] = x[(b0 + 1) * D_ + t];
        __syncthreads();
        int c = t & 127, ds = t >> 7;             // 8 d-slices of 128
        int d0 = ds * 128;
        float a00 = 0.f, a01 = 0.f, a10 = 0.f, a11 = 0.f;
#pragma unroll 4
        for (int d = d0; d < d0 + 128; d += 2) {
            float w0 = W_emb[(d + 0) * C_ + c];
            float w1 = W_emb[(d + 1) * C_ + c];
            a00 += xs[d] * w0;        a01 += xs[d + 1] * w1;
            a10 += xs[1024 + d] * w0; a11 += xs[1024 + d + 1] * w1;
        }
        part[ds * 128 + c] = a00 + a01;
        part[1024 + ds * 128 + c] = a10 + a11;
        __syncthreads();
        if (t < 256) {
            int bb = t >> 7, cc = t & 127;
            float h = b_emb[cc];
#pragma unroll
            for (int s = 0; s < 8; s++) h += part[bb * 1024 + s * 128 + cc];
            h0[bb * 128 + cc] = fmaxf(h, 0.f);
        }
        __syncthreads();
        int k0 = ds * 16;
        float p0 = 0.f, p1 = 0.f;
#pragma unroll
        for (int k = k0; k < k0 + 16; k++) {
            float w = W_conv[k * C_ + c];
            p0 += h0[k] * w;
            p1 += h0[128 + k] * w;
        }
        __syncthreads();
        part[ds * 128 + c] = p0;
        part[1024 + ds * 128 + c] = p1;
        __syncthreads();
        if (t < 256) {
            int bb = t >> 7, cc = t & 127;
            float a = 0.f;
#pragma unroll
            for (int s = 0; s < 8; s++) a += part[bb * 1024 + s * 128 + cc];
            g_w0[(b0 + bb) * C_ + cc] = a;
        }
    } else if (bid < 48) {
        int e = (bid - 32) * 1024 + t;            // 16*1024 == E_
        const unsigned* ew32 = (const unsigned*)eidx;
        int any = __syncthreads_or(ew32[2 * e + 1] != 0u);
        int is64 = !any;                          // int64 => high words all zero
        int s, d;
        if (is64) {
            const long long* p = (const long long*)eidx;
            s = (int)p[e]; d = (int)p[E_ + e];
        } else {
            const int* p = (const int*)eidx;
            s = p[e]; d = p[E_ + e];
        }
        g_src[e] = s; g_dst[e] = d;
        atomicAdd(&g_deg[d], 1);
        if (d == 0) g_flag3[s] = 1;
    }
    gsync(gen0, 1);

    // ======== P1: flag2 (0..15) || rowptr scan (16) || flag3 compact (17)
    //          || degree-rank claim + node-rank (18)
    if (bid < 16) {
        int e = bid * 1024 + t;
        if (g_flag3[g_dst[e]]) g_flag2[g_src[e]] = 1;
    } else if (bid == 16) {
        int d = g_deg[t];
        int incl = scan1(d, t, (int*)sm);
        g_rowptr[t + 1] = incl;
        if (t == 0) g_rowptr[0] = 0;
    } else if (bid == 17) {
        compact_flags(g_flag3, g_list3, &g_c3, t, (int*)sm);
    } else if (bid == 18) {
        int d = g_deg[t];                          // thread t handles node t
        int old = atomicExch(&g_flagd[d], 1);
        if (old == 0) {
            int r = atomicAdd(&g_nd, 1);
            g_degrank[d] = r;
            g_dval[r] = (float)d;
        }
        __syncthreads();
        g_nrank[t] = g_degrank[d];
    }
    gsync(gen0, 2);

    // ======== P2: csrfill (blocks 0..63, 16 nodes/block, 2 warps/node)
    //          || G-table build (blocks 64..130) || flag2 compact (131)
    if (bid < 64) {
        int grp  = t >> 6;                        // 16 node-groups
        int w    = (t >> 5) & 1;                  // warp within group (half of edges)
        int lane = t & 31;
        int n    = bid * 16 + grp;
        int* s_cnt = (int*)sm;                    // [16][2] half-totals
        bool act = (g_flag2[n] | g_flag3[n] | (n == 0));
        int e0 = w * (E_ / 2);
        if (act) {
            // pass 1: per-lane count over my half, one reduce at the end
            int tot = 0;
#pragma unroll 4
            for (int m = 0; m < 64; m++) {
                const int4 d4 = *(const int4*)&g_dst[e0 + m * 128 + lane * 4];
                tot += (d4.x == n) + (d4.y == n) + (d4.z == n) + (d4.w == n);
            }
#pragma unroll
            for (int off = 16; off > 0; off >>= 1)
                tot += __shfl_xor_sync(FULLM, tot, off);
            if (lane == 0) s_cnt[grp * 2 + w] = tot;
        }
        __syncthreads();
        if (act) {
            int base = g_rowptr[n] + (w ? s_cnt[grp * 2] : 0);
            int run = 0;                          // ballot-derived, no shfl chain
            unsigned lt = (1u << lane) - 1u;
            for (int m = 0; m < 64; m++) {
                int eb = e0 + m * 128 + lane * 4;
                const int4 d4 = *(const int4*)&g_dst[eb];
                const int4 s4 = *(const int4*)&g_src[eb];
                int m0 = (d4.x == n), m1 = (d4.y == n), m2 = (d4.z == n), m3 = (d4.w == n);
                unsigned bl0 = __ballot_sync(FULLM, m0), bl1 = __ballot_sync(FULLM, m1);
                unsigned bl2 = __ballot_sync(FULLM, m2), bl3 = __ballot_sync(FULLM, m3);
                int pos = base + run +
                          __popc(bl0 & lt) + __popc(bl1 & lt) +
                          __popc(bl2 & lt) + __popc(bl3 & lt);
                if (m0) { g_col[pos] = s4.x; g_nbrrank[pos] = g_nrank[s4.x]; pos++; }
                if (m1) { g_col[pos] = s4.y; g_nbrrank[pos] = g_nrank[s4.y]; pos++; }
                if (m2) { g_col[pos] = s4.z; g_nbrrank[pos] = g_nrank[s4.z]; pos++; }
                if (m3) { g_col[pos] = s4.w; g_nbrrank[pos] = g_nrank[s4.w]; }
                run += __popc(bl0) + __popc(bl1) + __popc(bl2) + __popc(bl3);
            }
        }
    } else if (bid < 131) {
        // G[rank][b][:] = relu(dval*w0[b]+bc) @ W_conv  (one 64-row tile per rank)
        int nd = g_nd;
        int c = t & 127, rg = t >> 7;
        float bc = b_conv[c];
        float (*As)[C_] = (float (*)[C_])sm;      // [64][128], row r == batch b
        for (int rank = bid - 64; rank < nd; rank += 67) {
            float dv = g_dval[rank];
            for (int r = rg * 8; r < rg * 8 + 8; r++)
                As[r][c] = fmaxf(dv * g_w0[r * C_ + c] + bc, 0.f);
            __syncthreads();
            unsigned long long acc2[8];
#pragma unroll
            for (int r = 0; r < 8; r++) acc2[r] = 0ull;
#pragma unroll 4
            for (int k = 0; k < C_; k += 4) {
                unsigned long long w01 = pack2(W_conv[(k + 0) * C_ + c],
                                               W_conv[(k + 1) * C_ + c]);
                unsigned long long w23 = pack2(W_conv[(k + 2) * C_ + c],
                                               W_conv[(k + 3) * C_ + c]);
#pragma unroll
                for (int r = 0; r < 8; r++) {
                    const ulonglong2 av = *(const ulonglong2*)&As[rg * 8 + r][k];
                    ffma2(acc2[r], av.x, w01);
                    ffma2(acc2[r], av.y, w23);
                }
            }
#pragma unroll
            for (int r = 0; r < 8; r++)
                g_G[(rank * B_ + rg * 8 + r) * C_ + c] = unpack_sum(acc2[r]);
            __syncthreads();
        }
    } else {
        compact_flags(g_flag2, g_list2, &g_c2, t, (int*)sm);
    }
    gsync(gen0, 3);

    // ======== P3: conv2 = aggregation of G rows, (node, batch-octet) groups ===
    {
        int cnt2 = g_c2;
        int items = cnt2 * 8;                     // (i2, b-octet) work items
        int gid8 = bid * 8 + (t >> 7);
        int c = t & 127;
        float bc = b_conv[c];
        for (int it = gid8; it < items; it += NB * 8) {
            int i = it >> 3, b0 = (it & 7) * 8;
            int n = g_list2[i];
            int s0 = g_rowptr[n], s1 = g_rowptr[n + 1];
            float a0 = 0.f, a1 = 0.f, a2 = 0.f, a3 = 0.f;
            float a4 = 0.f, a5 = 0.f, a6 = 0.f, a7 = 0.f;
#pragma unroll 2
            for (int q = s0; q < s1; q++) {
                const float* gp = &g_G[(g_nbrrank[q] * B_ + b0) * C_ + c];
                a0 += gp[0 * C_]; a1 += gp[1 * C_];
                a2 += gp[2 * C_]; a3 += gp[3 * C_];
                a4 += gp[4 * C_]; a5 += gp[5 * C_];
                a6 += gp[6 * C_]; a7 += gp[7 * C_];
            }
            float* hp = &g_H2[(b0 * N_ + n) * C_ + c];
            const int st = N_ * C_;
            hp[0 * st] = fmaxf(a0 + bc, 0.f); hp[1 * st] = fmaxf(a1 + bc, 0.f);
            hp[2 * st] = fmaxf(a2 + bc, 0.f); hp[3 * st] = fmaxf(a3 + bc, 0.f);
            hp[4 * st] = fmaxf(a4 + bc, 0.f); hp[5 * st] = fmaxf(a5 + bc, 0.f);
            hp[6 * st] = fmaxf(a6 + bc, 0.f); hp[7 * st] = fmaxf(a7 + bc, 0.f);
        }
    }
    gsync(gen0, 4);

    // ======== P4: conv3 fused agg + f32x2 GEMM + relu (one 8-row tile/block) ==
    {
        int cnt3 = g_c3;
        int M3 = B_ * cnt3;
        int ntiles = (M3 + 7) >> 3;
        int grp = t >> 7, c = t & 127;
        float bc = b_conv[c];
        float (*As)[C_] = (float (*)[C_])sm;      // [8][128], group grp owns row grp
        for (int tile = bid; tile < ntiles; tile += NB) {
            int rr = tile * 8 + grp;
            int b = 0, i = 0;
            float acc = 0.f;
            if (rr < M3) {
                b = rr / cnt3; i = rr - b * cnt3;
                int n = g_list3[i];
                int s0 = g_rowptr[n], s1 = g_rowptr[n + 1];
#pragma unroll 8
                for (int q = s0; q < s1; q++)
                    acc += g_H2[(b * N_ + g_col[q]) * C_ + c];
            }
            As[grp][c] = acc;
            __syncthreads();
            unsigned long long acc2 = 0ull;
#pragma unroll 4
            for (int k = 0; k < C_; k += 4) {
                unsigned long long w01 = pack2(W_conv[(k + 0) * C_ + c],
                                               W_conv[(k + 1) * C_ + c]);
                unsigned long long w23 = pack2(W_conv[(k + 2) * C_ + c],
                                               W_conv[(k + 3) * C_ + c]);
                const ulonglong2 av = *(const ulonglong2*)&As[grp][k];
                ffma2(acc2, av.x, w01);
                ffma2(acc2, av.y, w23);
            }
            if (rr < M3)
                g_H3[(b * N_ + g_list3[i]) * C_ + c] =
                    fmaxf(unpack_sum(acc2) + bc, 0.f);
            __syncthreads();
        }
    }
    gsync(gen0, 5);

    // ======== P5: conv4 agg (node 0) + GEMM + classifier (blocks 0..63)
    //          || clear scratch for next launch (blocks 64..67)
    if (bid < B_) {
        float* part = sm;            // [8][128]
        float* s4   = sm + 1024;     // [128]
        float* red  = sm + 1152;     // [128]
        int ks = t >> 7, c = t & 127;
        int s0 = g_rowptr[0], s1 = g_rowptr[1];
        float acc = 0.f;
        for (int q = s0 + ks; q < s1; q += 8)
            acc += g_H3[(bid * N_ + g_col[q]) * C_ + c];
        part[ks * 128 + c] = acc;
        __syncthreads();
        if (t < 128) {
            float a = 0.f;
#pragma unroll
            for (int s = 0; s < 8; s++) a += part[s * 128 + t];
            s4[t] = a;
        }
        __syncthreads();
        int k0 = ks * 16;
        float p = 0.f;
#pragma unroll
        for (int k = k0; k < k0 + 16; k++) p += s4[k] * W_conv[k * C_ + c];
        __syncthreads();
        part[ks * 128 + c] = p;
        __syncthreads();
        if (t < 128) {
            float a2 = b_conv[t];
#pragma unroll
            for (int s = 0; s < 8; s++) a2 += part[s * 128 + t];
            red[t] = fmaxf(a2, 0.f) * W_cls[t];
        }
        __syncthreads();
#pragma unroll
        for (int off = 64; off > 0; off >>= 1) {
            if (t < off) red[t] += red[t + off];
            __syncthreads();
        }
        if (t == 0) out[bid] = red[0] + b_cls[0];
    } else if (bid == 64) {
        g_deg[t] = 0;
    } else if (bid == 65) {
        g_flag2[t] = 0;
    } else if (bid == 66) {
        g_flag3[t] = 0;
    } else if (bid == 67) {
        int nd = g_nd;
        if (t < nd) g_flagd[(int)g_dval[t]] = 0;
        __syncthreads();
        if (t == 0) g_nd = 0;
    }
}

extern "C" void kernel_launch(void* const* d_in, const int* in_sizes, int n_in,
                              void* d_out, int out_size) {
    (void)in_sizes; (void)n_in; (void)out_size;
    const float* x      = (const float*)d_in[0];
    const void*  eidx   = d_in[1];
    const float* W_emb  = (const float*)d_in[2];
    const float* b_emb  = (const float*)d_in[3];
    const float* W_conv = (const float*)d_in[4];
    const float* b_conv = (const float*)d_in[5];
    const float* W_cls  = (const float*)d_in[6];
    const float* b_cls  = (const float*)d_in[7];
    float* out = (float*)d_out;

    k_mega<<<NB, NT>>>(x, eidx, W_emb, b_emb, W_conv, b_conv, W_cls, b_cls, out);
}

// round 11
// speedup vs baseline: 4.7772x; 1.1246x over previous
#include <cuda_runtime.h>
#include <cuda_bf16.h>

// Problem constants (fixed by setup_inputs)
#define B_ 64
#define N_ 1024
#define E_ 16384
#define D_ 1024
#define C_ 128

#define NB 132          // 1 block per SM (<=148) -> co-residency guaranteed
#define NT 1024
#define FULLM 0xffffffffu
#define DMAXP1 (E_ + 1) // degree value range bound

// ---------------- device scratch (static, no allocations) ----------------
// deg/flag2/flag3/flagd/nd are cleared at the END of each launch (zero-init at load).
__device__ __align__(16) int g_src[E_];
__device__ __align__(16) int g_dst[E_];
__device__ int   g_deg[N_];
__device__ int   g_nrank[N_];           // node -> degree-rank
__device__ int   g_rowptr[N_ + 1];
__device__ int   g_cursor[N_];          // atomic fill cursors (= rowptr at P2 start)
__device__ int   g_col[E_];
__device__ int   g_nbrrank[E_];         // degree-rank of neighbor, per CSR slot
__device__ int   g_flag2[N_], g_flag3[N_];
__device__ int   g_list2[N_], g_list3[N_];
__device__ int   g_c2, g_c3;
__device__ int   g_flagd[DMAXP1];       // degree-value claimed flags
__device__ int   g_degrank[DMAXP1];     // degree value -> rank
__device__ float g_dval[N_];            // rank -> degree value (as float)
__device__ int   g_nd;                  // number of distinct degree values
__device__ float g_w0[B_ * C_];         // (h0 @ W_conv) per batch
__device__ float g_G[N_ * B_ * C_];     // G[rank][b][c] = H1row(deg) @ W_conv
__device__ float g_H2[B_ * N_ * C_];    // node-indexed (frontier2 rows valid)
__device__ float g_H3[B_ * N_ * C_];    // node-indexed (frontier3 rows valid)

// ---------------- software grid barrier (all blocks resident) ----------------
__device__ volatile unsigned g_gen;
__device__ unsigned          g_count;

__device__ __forceinline__ void gsync(unsigned gen0, unsigned k) {
    __syncthreads();
    if (threadIdx.x == 0) {
        __threadfence();
        if (atomicAdd(&g_count, 1u) == NB - 1u) {
            g_count = 0u;
            __threadfence();
            g_gen = gen0 + k;
        } else {
            while (g_gen != gen0 + k) { __nanosleep(32); }
        }
        __threadfence();
    }
    __syncthreads();
}

// ---------------- f32x2 packed FMA helpers (Blackwell) -----------------------
__device__ __forceinline__ void ffma2(unsigned long long& d,
                                      unsigned long long a, unsigned long long b) {
    asm("fma.rn.f32x2 %0, %1, %2, %0;" : "+l"(d) : "l"(a), "l"(b));
}
__device__ __forceinline__ unsigned long long pack2(float lo, float hi) {
    unsigned long long r;
    asm("mov.b64 %0, {%1, %2};" : "=l"(r) : "f"(lo), "f"(hi));
    return r;
}
__device__ __forceinline__ float unpack_sum(unsigned long long v) {
    float lo, hi;
    asm("mov.b64 {%0, %1}, %2;" : "=f"(lo), "=f"(hi) : "l"(v));
    return lo + hi;
}

// inclusive scan of one value per thread across 1024 threads (single block)
__device__ __forceinline__ int scan1(int v, int t, int* s) {
    s[t] = v;
    __syncthreads();
#pragma unroll
    for (int off = 1; off < NT; off <<= 1) {
        int u = (t >= off) ? s[t - off] : 0;
        __syncthreads();
        s[t] += u;
        __syncthreads();
    }
    int r = s[t];
    __syncthreads();
    return r;
}

__device__ __forceinline__ void compact_flags(const int* flags, int* list, int* cnt_out,
                                              int t, int* s) {
    int f = flags[t];
    int incl = scan1(f, t, s);
    if (f) list[incl - 1] = t;
    if (t == NT - 1) *cnt_out = incl;
}

__global__ __launch_bounds__(NT) void k_mega(
    const float* __restrict__ x, const void* __restrict__ eidx,
    const float* __restrict__ W_emb,  const float* __restrict__ b_emb,
    const float* __restrict__ W_conv, const float* __restrict__ b_conv,
    const float* __restrict__ W_cls,  const float* __restrict__ b_cls,
    float* __restrict__ out)
{
    __shared__ __align__(16) float sm[8192];     // 32 KB, unioned across phases
    const int t   = threadIdx.x;
    const int bid = blockIdx.x;
    const unsigned gen0 = g_gen;

    // ======== P0: embedding (blocks 0..31, 2 batches each)
    //          || edge convert + deg + flag3 (blocks 32..47)
    if (bid < 32) {
        int b0 = bid * 2;
        float* xs   = sm;             // [2][1024]
        float* part = sm + 2048;      // [2][8][128]
        float* h0   = sm + 4096;      // [2][128]
        xs[t] = x[b0 * D_ + t];
        xs[1024 + t] = x[(b0 + 1) * D_ + t];
        __syncthreads();
        int c = t & 127, ds = t >> 7;             // 8 d-slices of 128
        int d0 = ds * 128;
        float a00 = 0.f, a01 = 0.f, a10 = 0.f, a11 = 0.f;
#pragma unroll 4
        for (int d = d0; d < d0 + 128; d += 2) {
            float w0 = W_emb[(d + 0) * C_ + c];
            float w1 = W_emb[(d + 1) * C_ + c];
            a00 += xs[d] * w0;        a01 += xs[d + 1] * w1;
            a10 += xs[1024 + d] * w0; a11 += xs[1024 + d + 1] * w1;
        }
        part[ds * 128 + c] = a00 + a01;
        part[1024 + ds * 128 + c] = a10 + a11;
        __syncthreads();
        if (t < 256) {
            int bb = t >> 7, cc = t & 127;
            float h = b_emb[cc];
#pragma unroll
            for (int s = 0; s < 8; s++) h += part[bb * 1024 + s * 128 + cc];
            h0[bb * 128 + cc] = fmaxf(h, 0.f);
        }
        __syncthreads();
        int k0 = ds * 16;
        float p0 = 0.f, p1 = 0.f;
#pragma unroll
        for (int k = k0; k < k0 + 16; k++) {
            float w = W_conv[k * C_ + c];
            p0 += h0[k] * w;
            p1 += h0[128 + k] * w;
        }
        __syncthreads();
        part[ds * 128 + c] = p0;
        part[1024 + ds * 128 + c] = p1;
        __syncthreads();
        if (t < 256) {
            int bb = t >> 7, cc = t & 127;
            float a = 0.f;
#pragma unroll
            for (int s = 0; s < 8; s++) a += part[bb * 1024 + s * 128 + cc];
            g_w0[(b0 + bb) * C_ + cc] = a;
        }
    } else if (bid < 48) {
        int e = (bid - 32) * 1024 + t;            // 16*1024 == E_
        const unsigned* ew32 = (const unsigned*)eidx;
        int any = __syncthreads_or(ew32[2 * e + 1] != 0u);
        int is64 = !any;                          // int64 => high words all zero
        int s, d;
        if (is64) {
            const long long* p = (const long long*)eidx;
            s = (int)p[e]; d = (int)p[E_ + e];
        } else {
            const int* p = (const int*)eidx;
            s = p[e]; d = p[E_ + e];
        }
        g_src[e] = s; g_dst[e] = d;
        atomicAdd(&g_deg[d], 1);
        if (d == 0) g_flag3[s] = 1;
    }
    gsync(gen0, 1);

    // ======== P1: flag2 (0..15) || rowptr+cursor scan (16) || flag3 compact (17)
    //          || degree-rank claim + node-rank (18)
    if (bid < 16) {
        int e = bid * 1024 + t;
        if (g_flag3[g_dst[e]]) g_flag2[g_src[e]] = 1;
    } else if (bid == 16) {
        int d = g_deg[t];
        int incl = scan1(d, t, (int*)sm);
        g_rowptr[t + 1] = incl;
        g_cursor[t] = incl - d;                   // exclusive prefix = rowptr[t]
        if (t == 0) g_rowptr[0] = 0;
    } else if (bid == 17) {
        compact_flags(g_flag3, g_list3, &g_c3, t, (int*)sm);
    } else if (bid == 18) {
        int d = g_deg[t];                          // thread t handles node t
        int old = atomicExch(&g_flagd[d], 1);
        if (old == 0) {
            int r = atomicAdd(&g_nd, 1);
            g_degrank[d] = r;
            g_dval[r] = (float)d;
        }
        __syncthreads();
        g_nrank[t] = g_degrank[d];
    }
    gsync(gen0, 2);

    // ======== P2: csrfill edge-parallel (blocks 0..15, atomic cursors)
    //          || G-table build (blocks 16..130) || flag2 compact (131)
    if (bid < 16) {
        int e = bid * 1024 + t;
        int d = g_dst[e], s = g_src[e];
        int pos = atomicAdd(&g_cursor[d], 1);
        g_col[pos] = s;
        g_nbrrank[pos] = g_nrank[s];
    } else if (bid < 131) {
        // G[rank][b][:] = relu(dval*w0[b]+bc) @ W_conv  (one 64-row tile per rank)
        int nd = g_nd;
        int c = t & 127, rg = t >> 7;
        float bc = b_conv[c];
        float (*As)[C_] = (float (*)[C_])sm;      // [64][128], row r == batch b
        for (int rank = bid - 16; rank < nd; rank += 115) {
            float dv = g_dval[rank];
            for (int r = rg * 8; r < rg * 8 + 8; r++)
                As[r][c] = fmaxf(dv * g_w0[r * C_ + c] + bc, 0.f);
            __syncthreads();
            unsigned long long acc2[8];
#pragma unroll
            for (int r = 0; r < 8; r++) acc2[r] = 0ull;
#pragma unroll 4
            for (int k = 0; k < C_; k += 4) {
                unsigned long long w01 = pack2(W_conv[(k + 0) * C_ + c],
                                               W_conv[(k + 1) * C_ + c]);
                unsigned long long w23 = pack2(W_conv[(k + 2) * C_ + c],
                                               W_conv[(k + 3) * C_ + c]);
#pragma unroll
                for (int r = 0; r < 8; r++) {
                    const ulonglong2 av = *(const ulonglong2*)&As[rg * 8 + r][k];
                    ffma2(acc2[r], av.x, w01);
                    ffma2(acc2[r], av.y, w23);
                }
            }
#pragma unroll
            for (int r = 0; r < 8; r++)
                g_G[(rank * B_ + rg * 8 + r) * C_ + c] = unpack_sum(acc2[r]);
            __syncthreads();
        }
    } else {
        compact_flags(g_flag2, g_list2, &g_c2, t, (int*)sm);
    }
    gsync(gen0, 3);

    // ======== P3: conv2 = aggregation of G rows, 64-thread x 2-channel groups =
    {
        int cnt2 = g_c2;
        int items = cnt2 * 8;                     // (i2, b-octet) work items
        int gid = bid * 16 + (t >> 6);            // 2112 groups
        int c = t & 63;
        float bcL = b_conv[c], bcH = b_conv[c + 64];
        for (int it = gid; it < items; it += NB * 16) {
            int i = it >> 3, b0 = (it & 7) * 8;
            int n = g_list2[i];
            int s0 = g_rowptr[n], s1 = g_rowptr[n + 1];
            float a0 = 0.f, a1 = 0.f, a2 = 0.f, a3 = 0.f;
            float a4 = 0.f, a5 = 0.f, a6 = 0.f, a7 = 0.f;
            float h0 = 0.f, h1 = 0.f, h2 = 0.f, h3 = 0.f;
            float h4 = 0.f, h5 = 0.f, h6 = 0.f, h7 = 0.f;
#pragma unroll 1
            for (int q = s0; q < s1; q++) {
                const float* gp = &g_G[(g_nbrrank[q] * B_ + b0) * C_ + c];
                a0 += gp[0 * C_];      a1 += gp[1 * C_];
                a2 += gp[2 * C_];      a3 += gp[3 * C_];
                a4 += gp[4 * C_];      a5 += gp[5 * C_];
                a6 += gp[6 * C_];      a7 += gp[7 * C_];
                h0 += gp[0 * C_ + 64]; h1 += gp[1 * C_ + 64];
                h2 += gp[2 * C_ + 64]; h3 += gp[3 * C_ + 64];
                h4 += gp[4 * C_ + 64]; h5 += gp[5 * C_ + 64];
                h6 += gp[6 * C_ + 64]; h7 += gp[7 * C_ + 64];
            }
            float* hp = &g_H2[(b0 * N_ + n) * C_ + c];
            const int st = N_ * C_;
            hp[0 * st] = fmaxf(a0 + bcL, 0.f); hp[0 * st + 64] = fmaxf(h0 + bcH, 0.f);
            hp[1 * st] = fmaxf(a1 + bcL, 0.f); hp[1 * st + 64] = fmaxf(h1 + bcH, 0.f);
            hp[2 * st] = fmaxf(a2 + bcL, 0.f); hp[2 * st + 64] = fmaxf(h2 + bcH, 0.f);
            hp[3 * st] = fmaxf(a3 + bcL, 0.f); hp[3 * st + 64] = fmaxf(h3 + bcH, 0.f);
            hp[4 * st] = fmaxf(a4 + bcL, 0.f); hp[4 * st + 64] = fmaxf(h4 + bcH, 0.f);
            hp[5 * st] = fmaxf(a5 + bcL, 0.f); hp[5 * st + 64] = fmaxf(h5 + bcH, 0.f);
            hp[6 * st] = fmaxf(a6 + bcL, 0.f); hp[6 * st + 64] = fmaxf(h6 + bcH, 0.f);
            hp[7 * st] = fmaxf(a7 + bcL, 0.f); hp[7 * st + 64] = fmaxf(h7 + bcH, 0.f);
        }
    }
    gsync(gen0, 4);

    // ======== P4: conv3 fused agg + f32x2 GEMM + relu (one 8-row tile/block) ==
    {
        int cnt3 = g_c3;
        int M3 = B_ * cnt3;
        int ntiles = (M3 + 7) >> 3;
        int grp = t >> 7, c = t & 127;
        float bc = b_conv[c];
        float (*As)[C_] = (float (*)[C_])sm;      // [8][128], group grp owns row grp
        for (int tile = bid; tile < ntiles; tile += NB) {
            int rr = tile * 8 + grp;
            int b = 0, i = 0;
            float acc = 0.f;
            if (rr < M3) {
                b = rr / cnt3; i = rr - b * cnt3;
                int n = g_list3[i];
                int s0 = g_rowptr[n], s1 = g_rowptr[n + 1];
#pragma unroll 8
                for (int q = s0; q < s1; q++)
                    acc += g_H2[(b * N_ + g_col[q]) * C_ + c];
            }
            As[grp][c] = acc;
            __syncthreads();
            unsigned long long acc2 = 0ull;
#pragma unroll 4
            for (int k = 0; k < C_; k += 4) {
                unsigned long long w01 = pack2(W_conv[(k + 0) * C_ + c],
                                               W_conv[(k + 1) * C_ + c]);
                unsigned long long w23 = pack2(W_conv[(k + 2) * C_ + c],
                                               W_conv[(k + 3) * C_ + c]);
                const ulonglong2 av = *(const ulonglong2*)&As[grp][k];
                ffma2(acc2, av.x, w01);
                ffma2(acc2, av.y, w23);
            }
            if (rr < M3)
                g_H3[(b * N_ + g_list3[i]) * C_ + c] =
                    fmaxf(unpack_sum(acc2) + bc, 0.f);
            __syncthreads();
        }
    }
    gsync(gen0, 5);

    // ======== P5: conv4 agg (node 0) + GEMM + classifier (blocks 0..63)
    //          || clear scratch for next launch (blocks 64..67)
    if (bid < B_) {
        float* part = sm;            // [8][128]
        float* s4   = sm + 1024;     // [128]
        float* red  = sm + 1152;     // [128]
        int ks = t >> 7, c = t & 127;
        int s0 = g_rowptr[0], s1 = g_rowptr[1];
        float acc = 0.f;
        for (int q = s0 + ks; q < s1; q += 8)
            acc += g_H3[(bid * N_ + g_col[q]) * C_ + c];
        part[ks * 128 + c] = acc;
        __syncthreads();
        if (t < 128) {
            float a = 0.f;
#pragma unroll
            for (int s = 0; s < 8; s++) a += part[s * 128 + t];
            s4[t] = a;
        }
        __syncthreads();
        int k0 = ks * 16;
        float p = 0.f;
#pragma unroll
        for (int k = k0; k < k0 + 16; k++) p += s4[k] * W_conv[k * C_ + c];
        __syncthreads();
        part[ks * 128 + c] = p;
        __syncthreads();
        if (t < 128) {
            float a2 = b_conv[t];
#pragma unroll
            for (int s = 0; s < 8; s++) a2 += part[s * 128 + t];
            red[t] = fmaxf(a2, 0.f) * W_cls[t];
        }
        __syncthreads();
#pragma unroll
        for (int off = 64; off > 0; off >>= 1) {
            if (t < off) red[t] += red[t + off];
            __syncthreads();
        }
        if (t == 0) out[bid] = red[0] + b_cls[0];
    } else if (bid == 64) {
        g_deg[t] = 0;
    } else if (bid == 65) {
        g_flag2[t] = 0;
    } else if (bid == 66) {
        g_flag3[t] = 0;
    } else if (bid == 67) {
        int nd = g_nd;
        if (t < nd) g_flagd[(int)g_dval[t]] = 0;
        __syncthreads();
        if (t == 0) g_nd = 0;
    }
}

extern "C" void kernel_launch(void* const* d_in, const int* in_sizes, int n_in,
                              void* d_out, int out_size) {
    (void)in_sizes; (void)n_in; (void)out_size;
    const float* x      = (const float*)d_in[0];
    const void*  eidx   = d_in[1];
    const float* W_emb  = (const float*)d_in[2];
    const float* b_emb  = (const float*)d_in[3];
    const float* W_conv = (const float*)d_in[4];
    const float* b_conv = (const float*)d_in[5];
    const float* W_cls  = (const float*)d_in[6];
    const float* b_cls  = (const float*)d_in[7];
    float* out = (float*)d_out;

    k_mega<<<NB, NT>>>(x, eidx, W_emb, b_emb, W_conv, b_conv, W_cls, b_cls, out);
}